// round 14
// baseline (speedup 1.0000x reference)
#include <cuda_runtime.h>
#include <cstdint>
#include <math.h>
#include <mma.h>

using namespace nvcuda;

// ---------------- problem constants ----------------
#define NND   50000
#define FINN  100
#define NHID  100
#define EE    800000
#define NREL  200
#define BATCH 512
#define HD    100
#define D2    200

// ---------------- device scratch ----------------
__device__ int g_cnt[NND];
__device__ int g_cur[NND];
__device__ int g_rowptr[NND + 1];
__device__ int g_mask[NND];
__device__ int g_needflag[NND];
__device__ int g_need_idx[NND];
__device__ int g_need_list[NND];
__device__ int g_mask_list[BATCH];
__device__ int g_nneed, g_nmask;
__device__ int g_csr_e1[EE];
__device__ int g_csr_t[EE];
__device__ int g_t2map[NREL];

__device__ float g_vs1[2 * FINN], g_vd1[2 * FINN], g_vr1[2 * FINN];
__device__ float g_vs2[D2], g_vd2[D2], g_vr2[D2];
__device__ float g_he[BATCH * HD];
__device__ float g_pr1[2 * NREL];
__device__ float g_pr2[NREL];

// tf32, zero-padded GEMM operands
__device__ float g_xt[(size_t)(NND + 128) * 128];
__device__ float g_relt[256 * 128];
__device__ float g_Bent[400 * 128];
__device__ float g_Brel[400 * 128];
__device__ float g_Bsrc[240 * 128];
__device__ float g_Bl2[400 * 224];
__device__ float g_Brp2[240 * 224];

// C buffers (padded rows + 400-wide)
__device__ float g_relC[256 * 400];
__device__ float g_RT2g[256 * 224];
__device__ float g_rp2[256 * 400];
__device__ float g_big[(size_t)(NND + 128) * 400];
__device__ float g_xs1[(size_t)(NND + 128) * 400];
__device__ float g_l2[(size_t)(NND + 128) * 400];

__device__ float g_invn[NND];
__device__ float g_ps1[2 * NND], g_pd1[2 * NND];
__device__ float g_x1[(size_t)(NND + 128) * 224];
__device__ float g_ps2[NND], g_pd2[NND];
__device__ float g_x2[NND * D2];

__device__ __forceinline__ float lrelu_neg(float z) {
    return (z >= 0.f) ? -z : -0.2f * z;
}
__device__ __forceinline__ void cp16(unsigned int s, const float* g) {
    asm volatile("cp.async.cg.shared.global [%0], [%1], 16;\n" :: "r"(s), "l"(g));
}

// ---------------- kernels ----------------

__global__ void k_clear() {
    int i = blockIdx.x * blockDim.x + threadIdx.x;
    int stride = gridDim.x * blockDim.x;
    if (i == 0) { g_nneed = 0; g_nmask = 0; }
    for (int idx = i; idx < 5 * NND; idx += stride) {
        int which = idx / NND, j = idx % NND;
        if (which == 0) g_cnt[j] = 0;
        else if (which == 1) g_cur[j] = 0;
        else if (which == 2) g_mask[j] = 0;
        else if (which == 3) g_needflag[j] = 0;
        else g_need_list[j] = 0;
    }
}

// pack all B operands + rel table + x -> tf32 padded
__global__ void k_setup(const float* __restrict__ a_h,
                        const float* __restrict__ W_ent,
                        const float* __restrict__ W_rel,
                        const float* __restrict__ a_o,
                        const float* __restrict__ rel,
                        const float* __restrict__ x) {
    const int T1 = 400 * 128, T2 = 400 * 128, T3 = 240 * 128;
    const int T4 = 400 * 224, T5 = 240 * 224, T6 = 256 * 128;
    const int TP = T1 + T2 + T3 + T4 + T5 + T6;
    const int TX = (NND + 128) * 32;
    int idx = blockIdx.x * blockDim.x + threadIdx.x;
    int stride = gridDim.x * blockDim.x;
    for (int q = idx; q < TP + TX; q += stride) {
        if (q < TP) {
            int i = q;
            float v = 0.f;
            if (i < T1) {
                int r = i >> 7, k = i & 127;
                if (k < 100) v = (r < 200) ? a_h[(size_t)r * 300 + 100 + k]
                                           : W_ent[(size_t)k * 200 + (r - 200)];
                g_Bent[i] = wmma::__float_to_tf32(v);
            } else if (i < T1 + T2) {
                int j = i - T1; int r = j >> 7, k = j & 127;
                if (k < 100) v = (r < 200) ? a_h[(size_t)r * 300 + 200 + k]
                                           : W_rel[(size_t)k * 200 + (r - 200)];
                g_Brel[j] = wmma::__float_to_tf32(v);
            } else if (i < T1 + T2 + T3) {
                int j = i - T1 - T2; int r = j >> 7, k = j & 127;
                if (k < 100 && r < 200) v = a_h[(size_t)r * 300 + k];
                g_Bsrc[j] = wmma::__float_to_tf32(v);
            } else if (i < T1 + T2 + T3 + T4) {
                int j = i - T1 - T2 - T3; int r = j / 224, k = j % 224;
                if (k < 200) v = (r < 200) ? a_o[(size_t)r * 600 + 200 + k]
                                           : a_o[(size_t)(r - 200) * 600 + k];
                g_Bl2[j] = wmma::__float_to_tf32(v);
            } else if (i < T1 + T2 + T3 + T4 + T5) {
                int j = i - T1 - T2 - T3 - T4; int r = j / 224, k = j % 224;
                if (k < 200 && r < 200) v = a_o[(size_t)r * 600 + 400 + k];
                g_Brp2[j] = wmma::__float_to_tf32(v);
            } else {
                int j = i - T1 - T2 - T3 - T4 - T5; int r = j >> 7, k = j & 127;
                if (k < 100 && r < 200) v = rel[(size_t)r * 100 + k];
                g_relt[j] = wmma::__float_to_tf32(v);
            }
        } else {
            int i = q - TP;
            int row = i >> 5, c = i & 31;
            float4 v = make_float4(0.f, 0.f, 0.f, 0.f);
            if (row < NND && c < 25) {
                v = *(const float4*)(x + (size_t)row * FINN + c * 4);
                v.x = wmma::__float_to_tf32(v.x);
                v.y = wmma::__float_to_tf32(v.y);
                v.z = wmma::__float_to_tf32(v.z);
                v.w = wmma::__float_to_tf32(v.w);
            }
            ((float4*)g_xt)[i] = v;
        }
    }
}

// he table, t2map, combined logit vectors, mask set
__global__ void k_pre_small(const int* __restrict__ bi,
                            const float* __restrict__ wt2,
                            const float* __restrict__ bt2,
                            const int* __restrict__ etype,
                            const float* __restrict__ a_h,
                            const float* __restrict__ a2_h,
                            const float* __restrict__ a_o,
                            const float* __restrict__ a2_o) {
    int blk = blockIdx.x;
    int tid = threadIdx.x;  // 256
    if (blk < BATCH) {
        if (tid < HD) {
            float tf = (float)bi[blk * 4 + 3];
            float arg = __fadd_rn(__fmul_rn(tf, wt2[tid]), bt2[tid]);
            g_he[blk * HD + tid] = (float)cos((double)arg);
        }
    } else if (blk == BATCH) {
        if (tid < NREL) g_t2map[tid] = etype[tid];
    } else if (blk == BATCH + 1 || blk == BATCH + 2) {
        int h = blk - (BATCH + 1);
        if (tid < FINN) {
            float s0 = 0.f, s1 = 0.f, s2 = 0.f;
            for (int o = 0; o < NHID; o++) {
                float a2v = a2_h[h * NHID + o];
                const float* row = a_h + (size_t)h * NHID * 300 + (size_t)o * 300;
                s0 += row[tid] * a2v;
                s1 += row[100 + tid] * a2v;
                s2 += row[200 + tid] * a2v;
            }
            g_vs1[h * FINN + tid] = s0;
            g_vd1[h * FINN + tid] = s1;
            g_vr1[h * FINN + tid] = s2;
        }
    } else if (blk == BATCH + 3) {
        if (tid < D2) {
            float s0 = 0.f, s1 = 0.f, s2 = 0.f;
            for (int o = 0; o < D2; o++) {
                float a2v = a2_o[o];
                const float* row = a_o + (size_t)o * 600;
                s0 += row[tid] * a2v;
                s1 += row[200 + tid] * a2v;
                s2 += row[400 + tid] * a2v;
            }
            g_vs2[tid] = s0;
            g_vd2[tid] = s1;
            g_vr2[tid] = s2;
        }
    } else {
        for (int b = tid; b < BATCH; b += 256) {
            int node = bi[b * 4 + 2];
            g_mask[node] = 1;
            g_needflag[node] = 1;
        }
    }
}

// fused: hist_flags (blocks < HB) + xnvecs (blocks >= HB); 256 threads
#define HB 3125
__global__ void k_hx(const int* __restrict__ el, const float* __restrict__ x) {
    int tid = threadIdx.x;
    if (blockIdx.x < HB) {
        int e = blockIdx.x * 256 + tid;
        if (e >= EE) return;
        int e0 = el[e];
        int e1 = el[EE + e];
        atomicAdd(&g_cnt[e0], 1);
        if (g_mask[e0]) g_needflag[e1] = 1;
    } else {
        int warp = (blockIdx.x - HB) * 8 + (tid >> 5);
        int lane = tid & 31;
        if (warp >= NND) return;
        const float* row = x + (size_t)warp * FINN;
        float ss, a0 = 0.f, a1 = 0.f, b0 = 0.f, b1 = 0.f;
        float v0 = 0.f, v1 = 0.f, v2 = 0.f, v3 = 0.f;
        int k = lane;
        v0 = row[k];
        if (k + 32 < FINN) v1 = row[k + 32];
        if (k + 64 < FINN) v2 = row[k + 64];
        if (k + 96 < FINN) v3 = row[k + 96];
        ss = v0 * v0 + v1 * v1 + v2 * v2 + v3 * v3;
        a0 += v0 * g_vs1[k];        a1 += v0 * g_vs1[FINN + k];
        b0 += v0 * g_vd1[k];        b1 += v0 * g_vd1[FINN + k];
        if (k + 32 < FINN) {
            a0 += v1 * g_vs1[k+32]; a1 += v1 * g_vs1[FINN+k+32];
            b0 += v1 * g_vd1[k+32]; b1 += v1 * g_vd1[FINN+k+32];
        }
        if (k + 64 < FINN) {
            a0 += v2 * g_vs1[k+64]; a1 += v2 * g_vs1[FINN+k+64];
            b0 += v2 * g_vd1[k+64]; b1 += v2 * g_vd1[FINN+k+64];
        }
        if (k + 96 < FINN) {
            a0 += v3 * g_vs1[k+96]; a1 += v3 * g_vs1[FINN+k+96];
            b0 += v3 * g_vd1[k+96]; b1 += v3 * g_vd1[FINN+k+96];
        }
        for (int o = 16; o > 0; o >>= 1) {
            ss += __shfl_xor_sync(0xffffffffu, ss, o);
            a0 += __shfl_xor_sync(0xffffffffu, a0, o);
            a1 += __shfl_xor_sync(0xffffffffu, a1, o);
            b0 += __shfl_xor_sync(0xffffffffu, b0, o);
            b1 += __shfl_xor_sync(0xffffffffu, b1, o);
        }
        if (lane == 0) {
            g_invn[warp] = 1.f / fmaxf(sqrtf(ss), 1e-12f);
            g_ps1[warp] = a0;
            g_ps1[NND + warp] = a1;
            g_pd1[warp] = b0;
            g_pd1[NND + warp] = b1;
        }
    }
}

__global__ void k_scan_compact() {
    int t = threadIdx.x;  // 1024
    if (blockIdx.x == 0) {
        __shared__ int sm[1024];
        const int CH = 49;
        int base = t * CH;
        int s = 0;
        for (int i = 0; i < CH; i++) {
            int idx = base + i;
            if (idx < NND) s += g_cnt[idx];
        }
        sm[t] = s;
        __syncthreads();
        for (int off = 1; off < 1024; off <<= 1) {
            int v = 0;
            if (t >= off) v = sm[t - off];
            __syncthreads();
            if (t >= off) sm[t] += v;
            __syncthreads();
        }
        int run = (t == 0) ? 0 : sm[t - 1];
        for (int i = 0; i < CH; i++) {
            int idx = base + i;
            if (idx < NND) {
                g_rowptr[idx] = run;
                run += g_cnt[idx];
            }
        }
        if (t == 1023) g_rowptr[NND] = run;
    } else {
        int stride = (gridDim.x - 1) * 1024;
        for (int n = (blockIdx.x - 1) * 1024 + t; n < NND; n += stride) {
            if (g_needflag[n]) {
                int idx = atomicAdd(&g_nneed, 1);
                g_need_list[idx] = n;
                g_need_idx[n] = idx;
            }
            if (g_mask[n]) {
                int j = atomicAdd(&g_nmask, 1);
                g_mask_list[j] = n;
            }
        }
    }
}

__global__ void k_scatter(const int* __restrict__ el, const int* __restrict__ etype) {
    int e = blockIdx.x * blockDim.x + threadIdx.x;
    if (e >= EE) return;
    int e0 = el[e];
    int pos = g_rowptr[e0] + atomicAdd(&g_cur[e0], 1);
    g_csr_e1[pos] = el[EE + e];
    g_csr_t[pos] = etype[e];
}

// ---------------- persistent-A tf32 GEMM, K=128, multi-panel ----------------
// z=0: g_big = xt @ Bent^T (5 panels); z=1: g_relC = relt @ Brel^T (5 panels);
// z=2: g_xs1 = xt[need] @ Bsrc^T (3 panels). 320 thr; BM=128, BN=80; ldc=400.
__global__ void __launch_bounds__(320)
k_gemm_pa(const int* __restrict__ nneedp) {
    const int BM = 128, BN = 80, K = 128, LDS = 132, LDC = 400;
    extern __shared__ __align__(16) float smem[];
    float* As = smem;               // 128*132
    float* Bs = smem + BM * LDS;    // 80*132
    const float* A; const float* B; float* C;
    int M, panels;
    const int* glist = nullptr;
    int z = blockIdx.z;
    if (z == 0)      { A = g_xt;   B = g_Bent; C = g_big;  M = NND;     panels = 5; }
    else if (z == 1) { A = g_relt; B = g_Brel; C = g_relC; M = NREL;    panels = 5; }
    else             { A = g_xt;   B = g_Bsrc; C = g_xs1;  M = *nneedp; panels = 3;
                       glist = g_need_list; }
    int m0 = blockIdx.x * BM;
    if (m0 >= M) return;
    int tid = threadIdx.x;
    int wid = tid >> 5;
    int wm = wid & 1;
    int wn = wid >> 1;

    // load the whole A tile (128 x 128) once
    for (int i = tid; i < (BM * K) / 4; i += 320) {
        int m = i >> 5;
        int k4 = (i & 31) << 2;
        int row = glist ? glist[m0 + m] : (m0 + m);
        unsigned int daddr = (unsigned int)__cvta_generic_to_shared(&As[m * LDS + k4]);
        cp16(daddr, A + (size_t)row * K + k4);
    }
    // load B panel 0
    for (int i = tid; i < (BN * K) / 4; i += 320) {
        int o = i >> 5;
        int k4 = (i & 31) << 2;
        unsigned int daddr = (unsigned int)__cvta_generic_to_shared(&Bs[o * LDS + k4]);
        cp16(daddr, B + (size_t)o * K + k4);
    }
    asm volatile("cp.async.commit_group;\n" ::: "memory");
    asm volatile("cp.async.wait_group 0;\n" ::: "memory");
    __syncthreads();

    for (int pnl = 0; pnl < panels; pnl++) {
        wmma::fragment<wmma::accumulator, 16, 16, 8, float> c[4];
#pragma unroll
        for (int i = 0; i < 4; i++) wmma::fill_fragment(c[i], 0.f);
#pragma unroll
        for (int ks = 0; ks < K; ks += 8) {
            wmma::fragment<wmma::matrix_b, 16, 16, 8, wmma::precision::tf32,
                           wmma::col_major> b;
            wmma::load_matrix_sync(b, &Bs[(wn * 16) * LDS + ks], LDS);
#pragma unroll
            for (int i = 0; i < 4; i++) {
                wmma::fragment<wmma::matrix_a, 16, 16, 8, wmma::precision::tf32,
                               wmma::row_major> a;
                wmma::load_matrix_sync(a, &As[(wm * 64 + i * 16) * LDS + ks], LDS);
                wmma::mma_sync(c[i], a, b, c[i]);
            }
        }
        __syncthreads();  // all warps done reading Bs
        if (pnl + 1 < panels) {
            // prefetch next B panel (overlaps the C store below)
            for (int i = tid; i < (BN * K) / 4; i += 320) {
                int o = i >> 5;
                int k4 = (i & 31) << 2;
                unsigned int daddr =
                    (unsigned int)__cvta_generic_to_shared(&Bs[o * LDS + k4]);
                cp16(daddr, B + (size_t)((pnl + 1) * BN + o) * K + k4);
            }
            asm volatile("cp.async.commit_group;\n" ::: "memory");
        }
#pragma unroll
        for (int i = 0; i < 4; i++) {
            int gm0 = m0 + wm * 64 + i * 16;
            wmma::store_matrix_sync(&C[(size_t)gm0 * LDC + pnl * BN + wn * 16],
                                    c[i], LDC, wmma::mem_row_major);
        }
        if (pnl + 1 < panels) {
            asm volatile("cp.async.wait_group 0;\n" ::: "memory");
        }
        __syncthreads();
    }
}

// ---------------- pipelined tf32 GEMM for K=224 cases ----------------------
__global__ void __launch_bounds__(320)
k_gemm(const float* __restrict__ A, int lda,
       const float* __restrict__ B, int ldb,
       float* __restrict__ C, int ldc,
       const int* __restrict__ Mptr, int Mconst, int K) {
    const int BM = 128, BN = 80, BK = 32;
    const int LDS = BK + 4;
    __shared__ __align__(16) float As[2][BM * LDS];
    __shared__ __align__(16) float Bs[2][BN * LDS];
    int M = Mptr ? *Mptr : Mconst;
    int m0 = blockIdx.x * BM, o0 = blockIdx.y * BN;
    if (m0 >= M) return;
    int tid = threadIdx.x;
    int wid = tid >> 5;
    int wm = wid & 1;
    int wn = wid >> 1;

    wmma::fragment<wmma::accumulator, 16, 16, 8, float> c[4];
#pragma unroll
    for (int i = 0; i < 4; i++) wmma::fill_fragment(c[i], 0.f);

    auto prefetch = [&](int buf, int k0) {
#pragma unroll
        for (int s = 0; s < 4; s++) {
            int i = tid + s * 320;
            if (i < (BM * BK) / 4) {
                int m = i >> 3, k4 = (i & 7) << 2;
                unsigned int daddr = (unsigned int)__cvta_generic_to_shared(
                    &As[buf][m * LDS + k4]);
                cp16(daddr, A + (size_t)(m0 + m) * lda + k0 + k4);
            }
        }
#pragma unroll
        for (int s = 0; s < 2; s++) {
            int i = tid + s * 320;
            if (i < (BN * BK) / 4) {
                int o = i >> 3, k4 = (i & 7) << 2;
                unsigned int daddr = (unsigned int)__cvta_generic_to_shared(
                    &Bs[buf][o * LDS + k4]);
                cp16(daddr, B + (size_t)(o0 + o) * ldb + k0 + k4);
            }
        }
        asm volatile("cp.async.commit_group;\n" ::: "memory");
    };

    int niter = K / BK;
    prefetch(0, 0);
    for (int it = 0; it < niter; it++) {
        int buf = it & 1;
        if (it + 1 < niter) {
            prefetch(buf ^ 1, (it + 1) * BK);
            asm volatile("cp.async.wait_group 1;\n" ::: "memory");
        } else {
            asm volatile("cp.async.wait_group 0;\n" ::: "memory");
        }
        __syncthreads();
#pragma unroll
        for (int ks = 0; ks < BK; ks += 8) {
            wmma::fragment<wmma::matrix_b, 16, 16, 8, wmma::precision::tf32,
                           wmma::col_major> b;
            wmma::load_matrix_sync(b, &Bs[buf][(wn * 16) * LDS + ks], LDS);
#pragma unroll
            for (int i = 0; i < 4; i++) {
                wmma::fragment<wmma::matrix_a, 16, 16, 8, wmma::precision::tf32,
                               wmma::row_major> a;
                wmma::load_matrix_sync(a, &As[buf][(wm * 64 + i * 16) * LDS + ks], LDS);
                wmma::mma_sync(c[i], a, b, c[i]);
            }
        }
        __syncthreads();
    }
#pragma unroll
    for (int i = 0; i < 4; i++) {
        int gm0 = m0 + wm * 64 + i * 16;
        wmma::store_matrix_sync(&C[(size_t)gm0 * ldc + o0 + wn * 16], c[i],
                                ldc, wmma::mem_row_major);
    }
}

// fused: pr1 + RT2g build + pr2
__global__ void k_misc1(const float* __restrict__ rel) {
    int blk = blockIdx.x;
    int tid = threadIdx.x;  // 256
    if (blk < 50) {
        int w = blk * 8 + (tid >> 5);
        int lane = tid & 31;
        if (w >= 2 * NREL) return;
        int h = w / NREL, t = w % NREL;
        const float* rrow = rel + (size_t)t * 100;
        float s = 0.f;
        for (int kk = lane; kk < 100; kk += 32) s += rrow[kk] * g_vr1[h * FINN + kk];
        for (int o = 16; o > 0; o >>= 1) s += __shfl_xor_sync(0xffffffffu, s, o);
        if (lane == 0) g_pr1[h * NREL + t] = s;
    } else if (blk < 225) {
        int idx = (blk - 50) * 256 + tid;
        if (idx < NREL * 224) {
            int t = idx / 224, kk = idx % 224;
            float v = 0.f;
            if (kk < 200) v = g_relC[(size_t)g_t2map[t] * 400 + 200 + kk];
            g_RT2g[idx] = wmma::__float_to_tf32(v);
        }
    } else {
        int w = (blk - 225) * 8 + (tid >> 5);
        int lane = tid & 31;
        if (w >= NREL) return;
        const float* rrow = g_relC + (size_t)g_t2map[w] * 400 + 200;
        float s = 0.f;
        for (int kk = lane; kk < D2; kk += 32) s += rrow[kk] * g_vr2[kk];
        for (int o = 16; o > 0; o >>= 1) s += __shfl_xor_sync(0xffffffffu, s, o);
        if (lane == 0) g_pr2[w] = s;
    }
}

// layer-1 aggregation: staged weights + 4x-unrolled high-MLP edge loop
__global__ void k_agg1() {
    __shared__ float sw0[128], sw1[128];
    __shared__ int se1[128], st[128];
    __shared__ float redA[4], redB[4];
    int d = threadIdx.x;  // 128
    int wid = d >> 5, lane = d & 31;
    int nneed = g_nneed;
    for (int i = blockIdx.x; i < nneed; i += gridDim.x) {
        int n = g_need_list[i];
        float ps_a = g_ps1[n];
        float ps_b = g_ps1[NND + n];
        int s = g_rowptr[n], e = g_rowptr[n + 1];
        float acc0 = 0.f, acc1 = 0.f, ws0 = 0.f, ws1 = 0.f;
        for (int cs = s; cs < e; cs += 128) {
            int cnt = min(128, e - cs);
            __syncthreads();
            if (d < cnt) {
                int e1 = g_csr_e1[cs + d];
                int t = g_csr_t[cs + d];
                se1[d] = e1;
                st[d] = t;
                sw0[d] = expf(lrelu_neg(ps_a + g_pd1[e1] + g_pr1[t]));
                sw1[d] = expf(lrelu_neg(ps_b + g_pd1[NND + e1] + g_pr1[NREL + t]));
            }
            __syncthreads();
            int jj = 0;
            if (d < NHID) {
                float a0x = 0.f, a0y = 0.f, a1x = 0.f, a1y = 0.f;
                float w0x = 0.f, w0y = 0.f, w1x = 0.f, w1y = 0.f;
                for (; jj + 4 <= cnt; jj += 4) {
                    const float* B0 = g_big + (size_t)se1[jj] * 400;
                    const float* B1 = g_big + (size_t)se1[jj + 1] * 400;
                    const float* B2 = g_big + (size_t)se1[jj + 2] * 400;
                    const float* B3 = g_big + (size_t)se1[jj + 3] * 400;
                    const float* R0 = g_relC + (size_t)st[jj] * 400;
                    const float* R1 = g_relC + (size_t)st[jj + 1] * 400;
                    const float* R2 = g_relC + (size_t)st[jj + 2] * 400;
                    const float* R3 = g_relC + (size_t)st[jj + 3] * 400;
                    float b00 = B0[d], b01 = B1[d], b02 = B2[d], b03 = B3[d];
                    float b10 = B0[100 + d], b11 = B1[100 + d];
                    float b12 = B2[100 + d], b13 = B3[100 + d];
                    float r00 = R0[d], r01 = R1[d], r02 = R2[d], r03 = R3[d];
                    float r10 = R0[100 + d], r11 = R1[100 + d];
                    float r12 = R2[100 + d], r13 = R3[100 + d];
                    float w00 = sw0[jj], w01 = sw0[jj + 1];
                    float w02 = sw0[jj + 2], w03 = sw0[jj + 3];
                    float w10 = sw1[jj], w11 = sw1[jj + 1];
                    float w12 = sw1[jj + 2], w13 = sw1[jj + 3];
                    a0x += w00 * (b00 + r00);
                    a0y += w01 * (b01 + r01);
                    a0x += w02 * (b02 + r02);
                    a0y += w03 * (b03 + r03);
                    a1x += w10 * (b10 + r10);
                    a1y += w11 * (b11 + r11);
                    a1x += w12 * (b12 + r12);
                    a1y += w13 * (b13 + r13);
                    w0x += w00 + w02;
                    w0y += w01 + w03;
                    w1x += w10 + w12;
                    w1y += w11 + w13;
                }
                acc0 += a0x + a0y;
                acc1 += a1x + a1y;
                ws0 += w0x + w0y;
                ws1 += w1x + w1y;
                for (; jj < cnt; jj++) {
                    float w0 = sw0[jj], w1 = sw1[jj];
                    ws0 += w0;
                    ws1 += w1;
                    const float* bigrow = g_big + (size_t)se1[jj] * 400;
                    const float* rprow = g_relC + (size_t)st[jj] * 400;
                    acc0 += w0 * (bigrow[d] + rprow[d]);
                    acc1 += w1 * (bigrow[100 + d] + rprow[100 + d]);
                }
            }
        }
        float h0e = 0.f, h1e = 0.f;
        if (d < NHID) {
            float h0 = (g_xs1[(size_t)i * 400 + d] * ws0 + acc0) / (ws0 + 1e-12f);
            float h1 = (g_xs1[(size_t)i * 400 + 100 + d] * ws1 + acc1) / (ws1 + 1e-12f);
            h0e = (h0 > 0.f) ? h0 : expm1f(h0);
            h1e = (h1 > 0.f) ? h1 : expm1f(h1);
            g_x1[(size_t)i * 224 + d] = wmma::__float_to_tf32(h0e);
            g_x1[(size_t)i * 224 + 100 + d] = wmma::__float_to_tf32(h1e);
        } else if (d >= 100 && d < 124) {
            g_x1[(size_t)i * 224 + 100 + d] = 0.f;
        }
        float pa = 0.f, pb = 0.f;
        if (d < NHID) {
            pa = h0e * g_vd2[d] + h1e * g_vd2[100 + d];
            pb = h0e * g_vs2[d] + h1e * g_vs2[100 + d];
        }
        for (int o = 16; o > 0; o >>= 1) {
            pa += __shfl_xor_sync(0xffffffffu, pa, o);
            pb += __shfl_xor_sync(0xffffffffu, pb, o);
        }
        if (lane == 0) { redA[wid] = pa; redB[wid] = pb; }
        __syncthreads();
        if (d == 0) {
            g_pd2[i] = redA[0] + redA[1] + redA[2] + redA[3];
            g_ps2[i] = redB[0] + redB[1] + redB[2] + redB[3];
        }
        __syncthreads();
    }
}

// layer-2 aggregation: staged weights + 4x-unrolled edge loop
__global__ void k_agg2() {
    __shared__ float sw[256];
    __shared__ int si1[256], st[256];
    int d = threadIdx.x;  // 256
    int nmask = g_nmask;
    for (int m = blockIdx.x; m < nmask; m += gridDim.x) {
        int n = g_mask_list[m];
        int ii = g_need_idx[n];
        float ps = g_ps2[ii];
        int s = g_rowptr[n], e = g_rowptr[n + 1];
        float acc = 0.f, ws = 0.f;
        for (int cs = s; cs < e; cs += 256) {
            int cnt = min(256, e - cs);
            __syncthreads();
            if (d < cnt) {
                int e1 = g_csr_e1[cs + d];
                int t = g_csr_t[cs + d];
                int i1 = g_need_idx[e1];
                si1[d] = i1;
                st[d] = t;
                sw[d] = expf(lrelu_neg(ps + g_pd2[i1] + g_pr2[t]));
            }
            __syncthreads();
            if (d < D2) {
                int jj = 0;
                float ax = 0.f, ay = 0.f, wx = 0.f, wy = 0.f;
                for (; jj + 4 <= cnt; jj += 4) {
                    const float* L0 = g_l2 + (size_t)si1[jj] * 400;
                    const float* L1 = g_l2 + (size_t)si1[jj + 1] * 400;
                    const float* L2 = g_l2 + (size_t)si1[jj + 2] * 400;
                    const float* L3 = g_l2 + (size_t)si1[jj + 3] * 400;
                    const float* R0 = g_rp2 + (size_t)st[jj] * 400;
                    const float* R1 = g_rp2 + (size_t)st[jj + 1] * 400;
                    const float* R2 = g_rp2 + (size_t)st[jj + 2] * 400;
                    const float* R3 = g_rp2 + (size_t)st[jj + 3] * 400;
                    float l0 = L0[d], l1 = L1[d], l2 = L2[d], l3 = L3[d];
                    float r0 = R0[d], r1 = R1[d], r2 = R2[d], r3 = R3[d];
                    float w0 = sw[jj], w1 = sw[jj + 1], w2 = sw[jj + 2], w3 = sw[jj + 3];
                    ax += w0 * (l0 + r0);
                    ay += w1 * (l1 + r1);
                    ax += w2 * (l2 + r2);
                    ay += w3 * (l3 + r3);
                    wx += w0 + w2;
                    wy += w1 + w3;
                }
                acc += ax + ay;
                ws += wx + wy;
                for (; jj < cnt; jj++) {
                    float w = sw[jj];
                    ws += w;
                    acc += w * (g_l2[(size_t)si1[jj] * 400 + d] +
                                g_rp2[(size_t)st[jj] * 400 + d]);
                }
            }
        }
        if (d < D2) {
            float h = (g_l2[(size_t)ii * 400 + 200 + d] * ws + acc) / (ws + 1e-12f);
            g_x2[(size_t)ii * D2 + d] = (h > 0.f) ? h : expm1f(h);
        }
        __syncthreads();
    }
}

// fused: out (blocks < OB, warp per node) + his broadcast (blocks >= OB)
#define OB 6250
__global__ void k_outhis(float* __restrict__ out) {
    int tid = threadIdx.x;  // 256
    if (blockIdx.x < OB) {
        int w = blockIdx.x * 8 + (tid >> 5);
        int lane = tid & 31;
        if (w >= NND) return;
        int n = w;
        int msk = g_mask[n];
        int ii = msk ? g_need_idx[n] : 0;
        float inv = g_invn[n];
        const float* eur = g_big + (size_t)n * 400 + 200;
        const float* x2r = g_x2 + (size_t)ii * D2;
        float vals[7];
        float ss = 0.f;
#pragma unroll
        for (int r = 0; r < 7; r++) {
            int kk = lane + r * 32;
            float v = 0.f;
            if (kk < D2) {
                v = inv * eur[kk];
                if (msk) v += x2r[kk];
            }
            vals[r] = v;
            ss += v * v;
        }
        for (int o = 16; o > 0; o >>= 1) ss += __shfl_xor_sync(0xffffffffu, ss, o);
        float scale = 1.f / fmaxf(sqrtf(ss), 1e-12f);
        float* dst = out + (size_t)n * D2;
#pragma unroll
        for (int r = 0; r < 7; r++) {
            int kk = lane + r * 32;
            if (kk < D2) dst[kk] = vals[r] * scale;
        }
    } else {
        const size_t TOT4 = (size_t)BATCH * BATCH * (HD / 4);
        const size_t OFF4 = ((size_t)NND * D2) / 4;
        const float4* he4 = (const float4*)g_he;
        float4* o4 = (float4*)out;
        size_t idx = (size_t)(blockIdx.x - OB) * 256 + tid;
        size_t stride = (size_t)(gridDim.x - OB) * 256;
        for (size_t j = idx; j < TOT4; j += stride) {
            int c = (int)(j % (HD / 4));
            int b1 = (int)(j / ((size_t)BATCH * (HD / 4)));
            o4[OFF4 + j] = he4[b1 * (HD / 4) + c];
        }
    }
}

// ---------------- launcher ----------------
extern "C" void kernel_launch(void* const* d_in, const int* in_sizes, int n_in,
                              void* d_out, int out_size) {
    const float* x     = (const float*)d_in[0];
    const float* rel   = (const float*)d_in[1];
    const float* wt2   = (const float*)d_in[2];
    const float* bt2   = (const float*)d_in[3];
    const float* W_ent = (const float*)d_in[4];
    const float* a_h   = (const float*)d_in[5];
    const float* a2_h  = (const float*)d_in[6];
    const float* W_rel = (const float*)d_in[7];
    const float* a_o   = (const float*)d_in[8];
    const float* a2_o  = (const float*)d_in[9];
    const int* el      = (const int*)d_in[10];
    const int* et      = (const int*)d_in[11];
    const int* bi      = (const int*)d_in[12];
    float* out = (float*)d_out;
    (void)in_sizes; (void)n_in; (void)out_size;

    void* p;
    cudaGetSymbolAddress(&p, g_RT2g);  float* d_RT2g = (float*)p;
    cudaGetSymbolAddress(&p, g_rp2);   float* d_rp2  = (float*)p;
    cudaGetSymbolAddress(&p, g_Brp2);  float* d_Brp2 = (float*)p;
    cudaGetSymbolAddress(&p, g_Bl2);   float* d_Bl2  = (float*)p;
    cudaGetSymbolAddress(&p, g_x1);    float* d_x1   = (float*)p;
    cudaGetSymbolAddress(&p, g_l2);    float* d_l2   = (float*)p;
    cudaGetSymbolAddress(&p, g_nneed); const int* d_nneed = (const int*)p;

    const int GM = (NND + 127) / 128;  // 391
    const int SMEM_PA = (128 * 132 + 80 * 132) * 4;  // 109824 B
    cudaFuncSetAttribute(k_gemm_pa, cudaFuncAttributeMaxDynamicSharedMemorySize,
                         SMEM_PA);

    k_clear<<<256, 256>>>();
    k_setup<<<512, 256>>>(a_h, W_ent, W_rel, a_o, rel, x);
    k_pre_small<<<BATCH + 5, 256>>>(bi, wt2, bt2, et, a_h, a2_h, a_o, a2_o);
    k_hx<<<HB + (NND + 7) / 8, 256>>>(el, x);     // launch #4 (profiled)
    k_scan_compact<<<50, 1024>>>();
    k_scatter<<<(EE + 255) / 256, 256>>>(el, et);

    // mega persistent-A GEMM: z=0 big, z=1 relC, z=2 xs1
    k_gemm_pa<<<dim3(GM, 1, 3), 320, SMEM_PA>>>(d_nneed);

    k_misc1<<<250, 256>>>(rel);
    // rp2 = RT2g @ Brp2^T (K=224)
    k_gemm<<<dim3(2, 3), 320>>>(d_RT2g, 224, d_Brp2, 224, d_rp2, 400,
                                nullptr, NREL, 224);
    k_agg1<<<8192, 128>>>();
    // l2 = x1 @ Bl2^T (K=224)
    k_gemm<<<dim3(GM, 5), 320>>>(d_x1, 224, d_Bl2, 224, d_l2, 400,
                                 d_nneed, 0, 224);
    k_agg2<<<512, 256>>>();
    k_outhis<<<OB + 2048, 256>>>(out);
}

// round 15
// speedup vs baseline: 1.0450x; 1.0450x over previous
#include <cuda_runtime.h>
#include <cstdint>
#include <math.h>
#include <mma.h>

using namespace nvcuda;

// ---------------- problem constants ----------------
#define NND   50000
#define FINN  100
#define NHID  100
#define EE    800000
#define NREL  200
#define BATCH 512
#define HD    100
#define D2    200

// ---------------- device scratch ----------------
__device__ int g_cnt[NND];
__device__ int g_cur[NND];
__device__ int g_rowptr[NND + 1];
__device__ int g_mask[NND];
__device__ int g_needflag[NND];
__device__ int g_need_idx[NND];
__device__ int g_need_list[NND];
__device__ int g_mask_list[BATCH];
__device__ int g_nneed, g_nmask;
__device__ int g_csr_e1[EE];
__device__ int g_csr_t[EE];
__device__ int g_t2map[NREL];

__device__ float g_vs1[2 * FINN], g_vd1[2 * FINN], g_vr1[2 * FINN];
__device__ float g_vs2[D2], g_vd2[D2], g_vr2[D2];
__device__ float g_he[BATCH * HD];
__device__ float g_pr1[2 * NREL];
__device__ float g_pr2[NREL];

// tf32, zero-padded GEMM operands
__device__ float g_xt[(size_t)(NND + 128) * 128];
__device__ float g_relt[384 * 128];        // padded to 384 rows (BM=96 tiling)
__device__ float g_Bent[400 * 128];
__device__ float g_Brel[400 * 128];
__device__ float g_Bsrc[240 * 128];
__device__ float g_Bl2[400 * 224];
__device__ float g_Brp2[240 * 224];

// C buffers (padded rows + 400-wide)
__device__ float g_relC[384 * 400];        // padded to 384 rows
__device__ float g_RT2g[256 * 224];
__device__ float g_rp2[256 * 400];
__device__ float g_big[(size_t)(NND + 128) * 400];
__device__ float g_xs1[(size_t)(NND + 128) * 400];
__device__ float g_l2[(size_t)(NND + 128) * 400];

__device__ float g_invn[NND];
__device__ float g_ps1[2 * NND], g_pd1[2 * NND];
__device__ float g_x1[(size_t)(NND + 128) * 224];
__device__ float g_ps2[NND], g_pd2[NND];
__device__ float g_x2[NND * D2];

__device__ __forceinline__ float lrelu_neg(float z) {
    return (z >= 0.f) ? -z : -0.2f * z;
}
__device__ __forceinline__ void cp16(unsigned int s, const float* g) {
    asm volatile("cp.async.cg.shared.global [%0], [%1], 16;\n" :: "r"(s), "l"(g));
}

// ---------------- kernels ----------------

// blocks 0..255: clear; blocks 256..767: pack operands + x->tf32
__global__ void k_init(const float* __restrict__ a_h,
                       const float* __restrict__ W_ent,
                       const float* __restrict__ W_rel,
                       const float* __restrict__ a_o,
                       const float* __restrict__ rel,
                       const float* __restrict__ x) {
    int tid = threadIdx.x;  // 256
    if (blockIdx.x < 256) {
        int i = blockIdx.x * 256 + tid;
        int stride = 256 * 256;
        if (i == 0) { g_nneed = 0; g_nmask = 0; }
        for (int idx = i; idx < 5 * NND; idx += stride) {
            int which = idx / NND, j = idx % NND;
            if (which == 0) g_cnt[j] = 0;
            else if (which == 1) g_cur[j] = 0;
            else if (which == 2) g_mask[j] = 0;
            else if (which == 3) g_needflag[j] = 0;
            else g_need_list[j] = 0;
        }
    } else {
        const int T1 = 400 * 128, T2 = 400 * 128, T3 = 240 * 128;
        const int T4 = 400 * 224, T5 = 240 * 224, T6 = 384 * 128;
        const int TP = T1 + T2 + T3 + T4 + T5 + T6;
        const int TX = (NND + 128) * 32;
        int idx = (blockIdx.x - 256) * 256 + tid;
        int stride = 512 * 256;
        for (int q = idx; q < TP + TX; q += stride) {
            if (q < TP) {
                int i = q;
                float v = 0.f;
                if (i < T1) {
                    int r = i >> 7, k = i & 127;
                    if (k < 100) v = (r < 200) ? a_h[(size_t)r * 300 + 100 + k]
                                               : W_ent[(size_t)k * 200 + (r - 200)];
                    g_Bent[i] = wmma::__float_to_tf32(v);
                } else if (i < T1 + T2) {
                    int j = i - T1; int r = j >> 7, k = j & 127;
                    if (k < 100) v = (r < 200) ? a_h[(size_t)r * 300 + 200 + k]
                                               : W_rel[(size_t)k * 200 + (r - 200)];
                    g_Brel[j] = wmma::__float_to_tf32(v);
                } else if (i < T1 + T2 + T3) {
                    int j = i - T1 - T2; int r = j >> 7, k = j & 127;
                    if (k < 100 && r < 200) v = a_h[(size_t)r * 300 + k];
                    g_Bsrc[j] = wmma::__float_to_tf32(v);
                } else if (i < T1 + T2 + T3 + T4) {
                    int j = i - T1 - T2 - T3; int r = j / 224, k = j % 224;
                    if (k < 200) v = (r < 200) ? a_o[(size_t)r * 600 + 200 + k]
                                               : a_o[(size_t)(r - 200) * 600 + k];
                    g_Bl2[j] = wmma::__float_to_tf32(v);
                } else if (i < T1 + T2 + T3 + T4 + T5) {
                    int j = i - T1 - T2 - T3 - T4; int r = j / 224, k = j % 224;
                    if (k < 200 && r < 200) v = a_o[(size_t)r * 600 + 400 + k];
                    g_Brp2[j] = wmma::__float_to_tf32(v);
                } else {
                    int j = i - T1 - T2 - T3 - T4 - T5; int r = j >> 7, k = j & 127;
                    if (k < 100 && r < 200) v = rel[(size_t)r * 100 + k];
                    g_relt[j] = wmma::__float_to_tf32(v);
                }
            } else {
                int i = q - TP;
                int row = i >> 5, c = i & 31;
                float4 v = make_float4(0.f, 0.f, 0.f, 0.f);
                if (row < NND && c < 25) {
                    v = *(const float4*)(x + (size_t)row * FINN + c * 4);
                    v.x = wmma::__float_to_tf32(v.x);
                    v.y = wmma::__float_to_tf32(v.y);
                    v.z = wmma::__float_to_tf32(v.z);
                    v.w = wmma::__float_to_tf32(v.w);
                }
                ((float4*)g_xt)[i] = v;
            }
        }
    }
}

// he table, t2map, combined logit vectors, mask set
__global__ void k_pre_small(const int* __restrict__ bi,
                            const float* __restrict__ wt2,
                            const float* __restrict__ bt2,
                            const int* __restrict__ etype,
                            const float* __restrict__ a_h,
                            const float* __restrict__ a2_h,
                            const float* __restrict__ a_o,
                            const float* __restrict__ a2_o) {
    int blk = blockIdx.x;
    int tid = threadIdx.x;  // 256
    if (blk < BATCH) {
        if (tid < HD) {
            float tf = (float)bi[blk * 4 + 3];
            float arg = __fadd_rn(__fmul_rn(tf, wt2[tid]), bt2[tid]);
            g_he[blk * HD + tid] = (float)cos((double)arg);
        }
    } else if (blk == BATCH) {
        if (tid < NREL) g_t2map[tid] = etype[tid];
    } else if (blk == BATCH + 1 || blk == BATCH + 2) {
        int h = blk - (BATCH + 1);
        if (tid < FINN) {
            float s0 = 0.f, s1 = 0.f, s2 = 0.f;
            for (int o = 0; o < NHID; o++) {
                float a2v = a2_h[h * NHID + o];
                const float* row = a_h + (size_t)h * NHID * 300 + (size_t)o * 300;
                s0 += row[tid] * a2v;
                s1 += row[100 + tid] * a2v;
                s2 += row[200 + tid] * a2v;
            }
            g_vs1[h * FINN + tid] = s0;
            g_vd1[h * FINN + tid] = s1;
            g_vr1[h * FINN + tid] = s2;
        }
    } else if (blk == BATCH + 3) {
        if (tid < D2) {
            float s0 = 0.f, s1 = 0.f, s2 = 0.f;
            for (int o = 0; o < D2; o++) {
                float a2v = a2_o[o];
                const float* row = a_o + (size_t)o * 600;
                s0 += row[tid] * a2v;
                s1 += row[200 + tid] * a2v;
                s2 += row[400 + tid] * a2v;
            }
            g_vs2[tid] = s0;
            g_vd2[tid] = s1;
            g_vr2[tid] = s2;
        }
    } else {
        for (int b = tid; b < BATCH; b += 256) {
            int node = bi[b * 4 + 2];
            g_mask[node] = 1;
            g_needflag[node] = 1;
        }
    }
}

// fused: hist_flags (blocks < HB) + xnvecs (blocks >= HB); 256 threads
#define HB 3125
__global__ void k_hx(const int* __restrict__ el, const float* __restrict__ x) {
    int tid = threadIdx.x;
    if (blockIdx.x < HB) {
        int e = blockIdx.x * 256 + tid;
        if (e >= EE) return;
        int e0 = el[e];
        int e1 = el[EE + e];
        atomicAdd(&g_cnt[e0], 1);
        if (g_mask[e0]) g_needflag[e1] = 1;
    } else {
        int warp = (blockIdx.x - HB) * 8 + (tid >> 5);
        int lane = tid & 31;
        if (warp >= NND) return;
        const float* row = x + (size_t)warp * FINN;
        float ss, a0 = 0.f, a1 = 0.f, b0 = 0.f, b1 = 0.f;
        float v0 = 0.f, v1 = 0.f, v2 = 0.f, v3 = 0.f;
        int k = lane;
        v0 = row[k];
        if (k + 32 < FINN) v1 = row[k + 32];
        if (k + 64 < FINN) v2 = row[k + 64];
        if (k + 96 < FINN) v3 = row[k + 96];
        ss = v0 * v0 + v1 * v1 + v2 * v2 + v3 * v3;
        a0 += v0 * g_vs1[k];        a1 += v0 * g_vs1[FINN + k];
        b0 += v0 * g_vd1[k];        b1 += v0 * g_vd1[FINN + k];
        if (k + 32 < FINN) {
            a0 += v1 * g_vs1[k+32]; a1 += v1 * g_vs1[FINN+k+32];
            b0 += v1 * g_vd1[k+32]; b1 += v1 * g_vd1[FINN+k+32];
        }
        if (k + 64 < FINN) {
            a0 += v2 * g_vs1[k+64]; a1 += v2 * g_vs1[FINN+k+64];
            b0 += v2 * g_vd1[k+64]; b1 += v2 * g_vd1[FINN+k+64];
        }
        if (k + 96 < FINN) {
            a0 += v3 * g_vs1[k+96]; a1 += v3 * g_vs1[FINN+k+96];
            b0 += v3 * g_vd1[k+96]; b1 += v3 * g_vd1[FINN+k+96];
        }
        for (int o = 16; o > 0; o >>= 1) {
            ss += __shfl_xor_sync(0xffffffffu, ss, o);
            a0 += __shfl_xor_sync(0xffffffffu, a0, o);
            a1 += __shfl_xor_sync(0xffffffffu, a1, o);
            b0 += __shfl_xor_sync(0xffffffffu, b0, o);
            b1 += __shfl_xor_sync(0xffffffffu, b1, o);
        }
        if (lane == 0) {
            g_invn[warp] = 1.f / fmaxf(sqrtf(ss), 1e-12f);
            g_ps1[warp] = a0;
            g_ps1[NND + warp] = a1;
            g_pd1[warp] = b0;
            g_pd1[NND + warp] = b1;
        }
    }
}

__global__ void k_scan_compact() {
    int t = threadIdx.x;  // 1024
    if (blockIdx.x == 0) {
        __shared__ int sm[1024];
        const int CH = 49;
        int base = t * CH;
        int s = 0;
        for (int i = 0; i < CH; i++) {
            int idx = base + i;
            if (idx < NND) s += g_cnt[idx];
        }
        sm[t] = s;
        __syncthreads();
        for (int off = 1; off < 1024; off <<= 1) {
            int v = 0;
            if (t >= off) v = sm[t - off];
            __syncthreads();
            if (t >= off) sm[t] += v;
            __syncthreads();
        }
        int run = (t == 0) ? 0 : sm[t - 1];
        for (int i = 0; i < CH; i++) {
            int idx = base + i;
            if (idx < NND) {
                g_rowptr[idx] = run;
                run += g_cnt[idx];
            }
        }
        if (t == 1023) g_rowptr[NND] = run;
    } else {
        int stride = (gridDim.x - 1) * 1024;
        for (int n = (blockIdx.x - 1) * 1024 + t; n < NND; n += stride) {
            if (g_needflag[n]) {
                int idx = atomicAdd(&g_nneed, 1);
                g_need_list[idx] = n;
                g_need_idx[n] = idx;
            }
            if (g_mask[n]) {
                int j = atomicAdd(&g_nmask, 1);
                g_mask_list[j] = n;
            }
        }
    }
}

// ---------------- persistent-A tf32 GEMM, K=128, BM=96 (2 blocks/SM) -------
// z=0: big = xt@Bent^T (5 panels); z=1: relC = relt@Brel^T (5 panels);
// z=2: xs1 = xt[need]@Bsrc^T (3 panels); z=3: his broadcast (streaming).
__global__ void __launch_bounds__(320)
k_gemm_pa(const int* __restrict__ nneedp, float* __restrict__ out) {
    const int BM = 96, BN = 80, K = 128, LDS = 132, LDC = 400;
    int tid = threadIdx.x;
    int z = blockIdx.z;
    if (z == 3) {
        // his broadcast: out2[i,j,d] = he[i,d] (float4)
        const size_t TOT4 = (size_t)BATCH * BATCH * (HD / 4);
        const size_t OFF4 = ((size_t)NND * D2) / 4;
        const float4* he4 = (const float4*)g_he;
        float4* o4 = (float4*)out;
        size_t idx = (size_t)blockIdx.x * 320 + tid;
        size_t stride = (size_t)gridDim.x * 320;
        for (size_t j = idx; j < TOT4; j += stride) {
            int c = (int)(j % (HD / 4));
            int b1 = (int)(j / ((size_t)BATCH * (HD / 4)));
            o4[OFF4 + j] = he4[b1 * (HD / 4) + c];
        }
        return;
    }
    extern __shared__ __align__(16) float smem[];
    float* As = smem;               // 96*132
    float* Bs = smem + BM * LDS;    // 80*132
    const float* A; const float* B; float* C;
    int M, panels;
    const int* glist = nullptr;
    if (z == 0)      { A = g_xt;   B = g_Bent; C = g_big;  M = NND;     panels = 5; }
    else if (z == 1) { A = g_relt; B = g_Brel; C = g_relC; M = NREL;    panels = 5; }
    else             { A = g_xt;   B = g_Bsrc; C = g_xs1;  M = *nneedp; panels = 3;
                       glist = g_need_list; }
    int m0 = blockIdx.x * BM;
    if (m0 >= M) return;
    int wid = tid >> 5;
    int wm = wid & 1;
    int wn = wid >> 1;

    // load the whole A tile (96 x 128) once
    for (int i = tid; i < (BM * K) / 4; i += 320) {
        int m = i >> 5;
        int k4 = (i & 31) << 2;
        int row = glist ? glist[m0 + m] : (m0 + m);
        unsigned int daddr = (unsigned int)__cvta_generic_to_shared(&As[m * LDS + k4]);
        cp16(daddr, A + (size_t)row * K + k4);
    }
    // load B panel 0
    for (int i = tid; i < (BN * K) / 4; i += 320) {
        int o = i >> 5;
        int k4 = (i & 31) << 2;
        unsigned int daddr = (unsigned int)__cvta_generic_to_shared(&Bs[o * LDS + k4]);
        cp16(daddr, B + (size_t)o * K + k4);
    }
    asm volatile("cp.async.commit_group;\n" ::: "memory");
    asm volatile("cp.async.wait_group 0;\n" ::: "memory");
    __syncthreads();

    for (int pnl = 0; pnl < panels; pnl++) {
        wmma::fragment<wmma::accumulator, 16, 16, 8, float> c[3];
#pragma unroll
        for (int i = 0; i < 3; i++) wmma::fill_fragment(c[i], 0.f);
#pragma unroll
        for (int ks = 0; ks < K; ks += 8) {
            wmma::fragment<wmma::matrix_b, 16, 16, 8, wmma::precision::tf32,
                           wmma::col_major> b;
            wmma::load_matrix_sync(b, &Bs[(wn * 16) * LDS + ks], LDS);
#pragma unroll
            for (int i = 0; i < 3; i++) {
                wmma::fragment<wmma::matrix_a, 16, 16, 8, wmma::precision::tf32,
                               wmma::row_major> a;
                wmma::load_matrix_sync(a, &As[(wm * 48 + i * 16) * LDS + ks], LDS);
                wmma::mma_sync(c[i], a, b, c[i]);
            }
        }
        __syncthreads();  // all warps done reading Bs
        if (pnl + 1 < panels) {
            for (int i = tid; i < (BN * K) / 4; i += 320) {
                int o = i >> 5;
                int k4 = (i & 31) << 2;
                unsigned int daddr =
                    (unsigned int)__cvta_generic_to_shared(&Bs[o * LDS + k4]);
                cp16(daddr, B + (size_t)((pnl + 1) * BN + o) * K + k4);
            }
            asm volatile("cp.async.commit_group;\n" ::: "memory");
        }
#pragma unroll
        for (int i = 0; i < 3; i++) {
            int gm0 = m0 + wm * 48 + i * 16;
            wmma::store_matrix_sync(&C[(size_t)gm0 * LDC + pnl * BN + wn * 16],
                                    c[i], LDC, wmma::mem_row_major);
        }
        if (pnl + 1 < panels) {
            asm volatile("cp.async.wait_group 0;\n" ::: "memory");
        }
        __syncthreads();
    }
}

// fused: scatter (blocks < 3125) + misc1 (blocks 3125..3374); 256 threads
__global__ void k_scat_misc(const int* __restrict__ el,
                            const int* __restrict__ etype,
                            const float* __restrict__ rel) {
    int tid = threadIdx.x;
    if (blockIdx.x < 3125) {
        int e = blockIdx.x * 256 + tid;
        if (e >= EE) return;
        int e0 = el[e];
        int pos = g_rowptr[e0] + atomicAdd(&g_cur[e0], 1);
        g_csr_e1[pos] = el[EE + e];
        g_csr_t[pos] = etype[e];
        return;
    }
    int blk = blockIdx.x - 3125;
    if (blk < 50) {
        int w = blk * 8 + (tid >> 5);
        int lane = tid & 31;
        if (w >= 2 * NREL) return;
        int h = w / NREL, t = w % NREL;
        const float* rrow = rel + (size_t)t * 100;
        float s = 0.f;
        for (int kk = lane; kk < 100; kk += 32) s += rrow[kk] * g_vr1[h * FINN + kk];
        for (int o = 16; o > 0; o >>= 1) s += __shfl_xor_sync(0xffffffffu, s, o);
        if (lane == 0) g_pr1[h * NREL + t] = s;
    } else if (blk < 225) {
        int idx = (blk - 50) * 256 + tid;
        if (idx < NREL * 224) {
            int t = idx / 224, kk = idx % 224;
            float v = 0.f;
            if (kk < 200) v = g_relC[(size_t)g_t2map[t] * 400 + 200 + kk];
            g_RT2g[idx] = wmma::__float_to_tf32(v);
        }
    } else {
        int w = (blk - 225) * 8 + (tid >> 5);
        int lane = tid & 31;
        if (w >= NREL) return;
        const float* rrow = g_relC + (size_t)g_t2map[w] * 400 + 200;
        float s = 0.f;
        for (int kk = lane; kk < D2; kk += 32) s += rrow[kk] * g_vr2[kk];
        for (int o = 16; o > 0; o >>= 1) s += __shfl_xor_sync(0xffffffffu, s, o);
        if (lane == 0) g_pr2[w] = s;
    }
}

// layer-1 aggregation: staged weights + 4x-unrolled high-MLP edge loop
__global__ void k_agg1() {
    __shared__ float sw0[128], sw1[128];
    __shared__ int se1[128], st[128];
    __shared__ float redA[4], redB[4];
    int d = threadIdx.x;  // 128
    int wid = d >> 5, lane = d & 31;
    int nneed = g_nneed;
    for (int i = blockIdx.x; i < nneed; i += gridDim.x) {
        int n = g_need_list[i];
        float ps_a = g_ps1[n];
        float ps_b = g_ps1[NND + n];
        int s = g_rowptr[n], e = g_rowptr[n + 1];
        float acc0 = 0.f, acc1 = 0.f, ws0 = 0.f, ws1 = 0.f;
        for (int cs = s; cs < e; cs += 128) {
            int cnt = min(128, e - cs);
            __syncthreads();
            if (d < cnt) {
                int e1 = g_csr_e1[cs + d];
                int t = g_csr_t[cs + d];
                se1[d] = e1;
                st[d] = t;
                sw0[d] = expf(lrelu_neg(ps_a + g_pd1[e1] + g_pr1[t]));
                sw1[d] = expf(lrelu_neg(ps_b + g_pd1[NND + e1] + g_pr1[NREL + t]));
            }
            __syncthreads();
            int jj = 0;
            if (d < NHID) {
                float a0x = 0.f, a0y = 0.f, a1x = 0.f, a1y = 0.f;
                float w0x = 0.f, w0y = 0.f, w1x = 0.f, w1y = 0.f;
                for (; jj + 4 <= cnt; jj += 4) {
                    const float* B0 = g_big + (size_t)se1[jj] * 400;
                    const float* B1 = g_big + (size_t)se1[jj + 1] * 400;
                    const float* B2 = g_big + (size_t)se1[jj + 2] * 400;
                    const float* B3 = g_big + (size_t)se1[jj + 3] * 400;
                    const float* R0 = g_relC + (size_t)st[jj] * 400;
                    const float* R1 = g_relC + (size_t)st[jj + 1] * 400;
                    const float* R2 = g_relC + (size_t)st[jj + 2] * 400;
                    const float* R3 = g_relC + (size_t)st[jj + 3] * 400;
                    float b00 = B0[d], b01 = B1[d], b02 = B2[d], b03 = B3[d];
                    float b10 = B0[100 + d], b11 = B1[100 + d];
                    float b12 = B2[100 + d], b13 = B3[100 + d];
                    float r00 = R0[d], r01 = R1[d], r02 = R2[d], r03 = R3[d];
                    float r10 = R0[100 + d], r11 = R1[100 + d];
                    float r12 = R2[100 + d], r13 = R3[100 + d];
                    float w00 = sw0[jj], w01 = sw0[jj + 1];
                    float w02 = sw0[jj + 2], w03 = sw0[jj + 3];
                    float w10 = sw1[jj], w11 = sw1[jj + 1];
                    float w12 = sw1[jj + 2], w13 = sw1[jj + 3];
                    a0x += w00 * (b00 + r00);
                    a0y += w01 * (b01 + r01);
                    a0x += w02 * (b02 + r02);
                    a0y += w03 * (b03 + r03);
                    a1x += w10 * (b10 + r10);
                    a1y += w11 * (b11 + r11);
                    a1x += w12 * (b12 + r12);
                    a1y += w13 * (b13 + r13);
                    w0x += w00 + w02;
                    w0y += w01 + w03;
                    w1x += w10 + w12;
                    w1y += w11 + w13;
                }
                acc0 += a0x + a0y;
                acc1 += a1x + a1y;
                ws0 += w0x + w0y;
                ws1 += w1x + w1y;
                for (; jj < cnt; jj++) {
                    float w0 = sw0[jj], w1 = sw1[jj];
                    ws0 += w0;
                    ws1 += w1;
                    const float* bigrow = g_big + (size_t)se1[jj] * 400;
                    const float* rprow = g_relC + (size_t)st[jj] * 400;
                    acc0 += w0 * (bigrow[d] + rprow[d]);
                    acc1 += w1 * (bigrow[100 + d] + rprow[100 + d]);
                }
            }
        }
        float h0e = 0.f, h1e = 0.f;
        if (d < NHID) {
            float h0 = (g_xs1[(size_t)i * 400 + d] * ws0 + acc0) / (ws0 + 1e-12f);
            float h1 = (g_xs1[(size_t)i * 400 + 100 + d] * ws1 + acc1) / (ws1 + 1e-12f);
            h0e = (h0 > 0.f) ? h0 : expm1f(h0);
            h1e = (h1 > 0.f) ? h1 : expm1f(h1);
            g_x1[(size_t)i * 224 + d] = wmma::__float_to_tf32(h0e);
            g_x1[(size_t)i * 224 + 100 + d] = wmma::__float_to_tf32(h1e);
        } else if (d >= 100 && d < 124) {
            g_x1[(size_t)i * 224 + 100 + d] = 0.f;
        }
        float pa = 0.f, pb = 0.f;
        if (d < NHID) {
            pa = h0e * g_vd2[d] + h1e * g_vd2[100 + d];
            pb = h0e * g_vs2[d] + h1e * g_vs2[100 + d];
        }
        for (int o = 16; o > 0; o >>= 1) {
            pa += __shfl_xor_sync(0xffffffffu, pa, o);
            pb += __shfl_xor_sync(0xffffffffu, pb, o);
        }
        if (lane == 0) { redA[wid] = pa; redB[wid] = pb; }
        __syncthreads();
        if (d == 0) {
            g_pd2[i] = redA[0] + redA[1] + redA[2] + redA[3];
            g_ps2[i] = redB[0] + redB[1] + redB[2] + redB[3];
        }
        __syncthreads();
    }
}

// pipelined tf32 GEMM (K=224): z=0 l2 = x1@Bl2^T; z=1 rp2 = RT2g@Brp2^T
__global__ void __launch_bounds__(320)
k_gemm2(const int* __restrict__ nneedp) {
    const int BM = 128, BN = 80, BK = 32, K = 224;
    const int LDS = BK + 4;
    __shared__ __align__(16) float As[2][BM * LDS];
    __shared__ __align__(16) float Bs[2][BN * LDS];
    const float* A; const float* B; float* C;
    int M;
    if (blockIdx.z == 0) {
        A = g_x1; B = g_Bl2; C = g_l2; M = *nneedp;
    } else {
        if (blockIdx.x >= 2 || blockIdx.y >= 3) return;
        A = g_RT2g; B = g_Brp2; C = g_rp2; M = NREL;
    }
    int m0 = blockIdx.x * BM, o0 = blockIdx.y * BN;
    if (m0 >= M) return;
    int tid = threadIdx.x;
    int wid = tid >> 5;
    int wm = wid & 1;
    int wn = wid >> 1;

    wmma::fragment<wmma::accumulator, 16, 16, 8, float> c[4];
#pragma unroll
    for (int i = 0; i < 4; i++) wmma::fill_fragment(c[i], 0.f);

    auto prefetch = [&](int buf, int k0) {
#pragma unroll
        for (int s = 0; s < 4; s++) {
            int i = tid + s * 320;
            if (i < (BM * BK) / 4) {
                int m = i >> 3, k4 = (i & 7) << 2;
                unsigned int daddr = (unsigned int)__cvta_generic_to_shared(
                    &As[buf][m * LDS + k4]);
                cp16(daddr, A + (size_t)(m0 + m) * K + k0 + k4);
            }
        }
#pragma unroll
        for (int s = 0; s < 2; s++) {
            int i = tid + s * 320;
            if (i < (BN * BK) / 4) {
                int o = i >> 3, k4 = (i & 7) << 2;
                unsigned int daddr = (unsigned int)__cvta_generic_to_shared(
                    &Bs[buf][o * LDS + k4]);
                cp16(daddr, B + (size_t)(o0 + o) * K + k0 + k4);
            }
        }
        asm volatile("cp.async.commit_group;\n" ::: "memory");
    };

    int niter = K / BK;
    prefetch(0, 0);
    for (int it = 0; it < niter; it++) {
        int buf = it & 1;
        if (it + 1 < niter) {
            prefetch(buf ^ 1, (it + 1) * BK);
            asm volatile("cp.async.wait_group 1;\n" ::: "memory");
        } else {
            asm volatile("cp.async.wait_group 0;\n" ::: "memory");
        }
        __syncthreads();
#pragma unroll
        for (int ks = 0; ks < BK; ks += 8) {
            wmma::fragment<wmma::matrix_b, 16, 16, 8, wmma::precision::tf32,
                           wmma::col_major> b;
            wmma::load_matrix_sync(b, &Bs[buf][(wn * 16) * LDS + ks], LDS);
#pragma unroll
            for (int i = 0; i < 4; i++) {
                wmma::fragment<wmma::matrix_a, 16, 16, 8, wmma::precision::tf32,
                               wmma::row_major> a;
                wmma::load_matrix_sync(a, &As[buf][(wm * 64 + i * 16) * LDS + ks], LDS);
                wmma::mma_sync(c[i], a, b, c[i]);
            }
        }
        __syncthreads();
    }
#pragma unroll
    for (int i = 0; i < 4; i++) {
        int gm0 = m0 + wm * 64 + i * 16;
        wmma::store_matrix_sync(&C[(size_t)gm0 * 400 + o0 + wn * 16], c[i],
                                400, wmma::mem_row_major);
    }
}

// layer-2 aggregation: staged weights + 4x-unrolled edge loop
__global__ void k_agg2() {
    __shared__ float sw[256];
    __shared__ int si1[256], st[256];
    int d = threadIdx.x;  // 256
    int nmask = g_nmask;
    for (int m = blockIdx.x; m < nmask; m += gridDim.x) {
        int n = g_mask_list[m];
        int ii = g_need_idx[n];
        float ps = g_ps2[ii];
        int s = g_rowptr[n], e = g_rowptr[n + 1];
        float acc = 0.f, ws = 0.f;
        for (int cs = s; cs < e; cs += 256) {
            int cnt = min(256, e - cs);
            __syncthreads();
            if (d < cnt) {
                int e1 = g_csr_e1[cs + d];
                int t = g_csr_t[cs + d];
                int i1 = g_need_idx[e1];
                si1[d] = i1;
                st[d] = t;
                sw[d] = expf(lrelu_neg(ps + g_pd2[i1] + g_pr2[t]));
            }
            __syncthreads();
            if (d < D2) {
                int jj = 0;
                float ax = 0.f, ay = 0.f, wx = 0.f, wy = 0.f;
                for (; jj + 4 <= cnt; jj += 4) {
                    const float* L0 = g_l2 + (size_t)si1[jj] * 400;
                    const float* L1 = g_l2 + (size_t)si1[jj + 1] * 400;
                    const float* L2 = g_l2 + (size_t)si1[jj + 2] * 400;
                    const float* L3 = g_l2 + (size_t)si1[jj + 3] * 400;
                    const float* R0 = g_rp2 + (size_t)st[jj] * 400;
                    const float* R1 = g_rp2 + (size_t)st[jj + 1] * 400;
                    const float* R2 = g_rp2 + (size_t)st[jj + 2] * 400;
                    const float* R3 = g_rp2 + (size_t)st[jj + 3] * 400;
                    float l0 = L0[d], l1 = L1[d], l2 = L2[d], l3 = L3[d];
                    float r0 = R0[d], r1 = R1[d], r2 = R2[d], r3 = R3[d];
                    float w0 = sw[jj], w1 = sw[jj + 1], w2 = sw[jj + 2], w3 = sw[jj + 3];
                    ax += w0 * (l0 + r0);
                    ay += w1 * (l1 + r1);
                    ax += w2 * (l2 + r2);
                    ay += w3 * (l3 + r3);
                    wx += w0 + w2;
                    wy += w1 + w3;
                }
                acc += ax + ay;
                ws += wx + wy;
                for (; jj < cnt; jj++) {
                    float w = sw[jj];
                    ws += w;
                    acc += w * (g_l2[(size_t)si1[jj] * 400 + d] +
                                g_rp2[(size_t)st[jj] * 400 + d]);
                }
            }
        }
        if (d < D2) {
            float h = (g_l2[(size_t)ii * 400 + 200 + d] * ws + acc) / (ws + 1e-12f);
            g_x2[(size_t)ii * D2 + d] = (h > 0.f) ? h : expm1f(h);
        }
        __syncthreads();
    }
}

// warp-per-node: out[n] = l2norm(invn[n]*euraw[n] + mask*x2[n])
__global__ void k_out(float* __restrict__ out) {
    int w = (blockIdx.x * blockDim.x + threadIdx.x) >> 5;
    int lane = threadIdx.x & 31;
    if (w >= NND) return;
    int n = w;
    int msk = g_mask[n];
    int ii = msk ? g_need_idx[n] : 0;
    float inv = g_invn[n];
    const float* eur = g_big + (size_t)n * 400 + 200;
    const float* x2r = g_x2 + (size_t)ii * D2;
    float vals[7];
    float ss = 0.f;
#pragma unroll
    for (int r = 0; r < 7; r++) {
        int kk = lane + r * 32;
        float v = 0.f;
        if (kk < D2) {
            v = inv * eur[kk];
            if (msk) v += x2r[kk];
        }
        vals[r] = v;
        ss += v * v;
    }
    for (int o = 16; o > 0; o >>= 1) ss += __shfl_xor_sync(0xffffffffu, ss, o);
    float scale = 1.f / fmaxf(sqrtf(ss), 1e-12f);
    float* dst = out + (size_t)n * D2;
#pragma unroll
    for (int r = 0; r < 7; r++) {
        int kk = lane + r * 32;
        if (kk < D2) dst[kk] = vals[r] * scale;
    }
}

// ---------------- launcher ----------------
extern "C" void kernel_launch(void* const* d_in, const int* in_sizes, int n_in,
                              void* d_out, int out_size) {
    const float* x     = (const float*)d_in[0];
    const float* rel   = (const float*)d_in[1];
    const float* wt2   = (const float*)d_in[2];
    const float* bt2   = (const float*)d_in[3];
    const float* W_ent = (const float*)d_in[4];
    const float* a_h   = (const float*)d_in[5];
    const float* a2_h  = (const float*)d_in[6];
    const float* W_rel = (const float*)d_in[7];
    const float* a_o   = (const float*)d_in[8];
    const float* a2_o  = (const float*)d_in[9];
    const int* el      = (const int*)d_in[10];
    const int* et      = (const int*)d_in[11];
    const int* bi      = (const int*)d_in[12];
    float* out = (float*)d_out;
    (void)in_sizes; (void)n_in; (void)out_size;

    void* p;
    cudaGetSymbolAddress(&p, g_nneed); const int* d_nneed = (const int*)p;

    const int GM96 = (NND + 95) / 96;     // 521
    const int GM = (NND + 127) / 128;     // 391
    const int SMEM_PA = (96 * 132 + 80 * 132) * 4;  // 92928 B -> 2 blocks/SM
    cudaFuncSetAttribute(k_gemm_pa, cudaFuncAttributeMaxDynamicSharedMemorySize,
                         SMEM_PA);

    k_init<<<768, 256>>>(a_h, W_ent, W_rel, a_o, rel, x);
    k_pre_small<<<BATCH + 5, 256>>>(bi, wt2, bt2, et, a_h, a2_h, a_o, a2_o);
    k_hx<<<HB + (NND + 7) / 8, 256>>>(el, x);
    k_scan_compact<<<50, 1024>>>();            // launch #4 (profiled)

    // persistent-A GEMMs + his broadcast in one launch
    k_gemm_pa<<<dim3(GM96, 1, 4), 320, SMEM_PA>>>(d_nneed, out);

    k_scat_misc<<<3125 + 250, 256>>>(el, et, rel);
    k_agg1<<<8192, 128>>>();
    k_gemm2<<<dim3(GM, 5, 2), 320>>>(d_nneed);
    k_agg2<<<512, 256>>>();
    k_out<<<(NND * 32 + 255) / 256, 256>>>(out);
}

// round 17
// speedup vs baseline: 1.0902x; 1.0433x over previous
#include <cuda_runtime.h>
#include <cstdint>
#include <math.h>
#include <mma.h>

using namespace nvcuda;

// ---------------- problem constants ----------------
#define NND   50000
#define FINN  100
#define NHID  100
#define EE    800000
#define NREL  200
#define BATCH 512
#define HD    100
#define D2    200

// ---------------- device scratch ----------------
__device__ int g_cnt[NND];
__device__ int g_cur[NND];
__device__ int g_rowptr[NND + 1];
__device__ int g_mask[NND];
__device__ int g_needflag[NND];
__device__ int g_need_idx[NND];
__device__ int g_need_list[NND];
__device__ int g_mask_list[BATCH];
__device__ int g_nneed, g_nmask;
__device__ int g_csr_e1[EE];
__device__ int g_csr_t[EE];
__device__ int g_t2map[NREL];

__device__ float g_vs1[2 * FINN], g_vd1[2 * FINN], g_vr1[2 * FINN];
__device__ float g_vs2[D2], g_vd2[D2], g_vr2[D2];
__device__ float g_he[BATCH * HD];
__device__ float g_pr1[2 * NREL];
__device__ float g_pr2[NREL];

// tf32, zero-padded GEMM operands
__device__ float g_xt[(size_t)(NND + 128) * 128];
__device__ float g_relt[384 * 128];
__device__ float g_Bent[400 * 128];
__device__ float g_Brel[400 * 128];
__device__ float g_Bsrc[240 * 128];
__device__ float g_Bl2[400 * 224];
__device__ float g_Brp2[240 * 224];

// C buffers (padded rows + 400-wide)
__device__ float g_relC[384 * 400];
__device__ float g_RT2g[256 * 224];
__device__ float g_rp2[256 * 400];
__device__ float g_big[(size_t)(NND + 128) * 400];
__device__ float g_xs1[(size_t)(NND + 128) * 400];
__device__ float g_l2[(size_t)(NND + 128) * 400];

__device__ float g_invn[NND];
__device__ float g_ps1[2 * NND], g_pd1[2 * NND];
__device__ float g_x1[(size_t)(NND + 128) * 224];
__device__ float g_ps2[NND], g_pd2[NND];
__device__ float g_x2[NND * D2];

__device__ __forceinline__ float lrelu_neg(float z) {
    return (z >= 0.f) ? -z : -0.2f * z;
}
__device__ __forceinline__ void cp16(unsigned int s, const float* g) {
    asm volatile("cp.async.cg.shared.global [%0], [%1], 16;\n" :: "r"(s), "l"(g));
}

// ---------------- kernels ----------------

// blocks 0..255: clear; blocks 256..767: pack operands + x->tf32
__global__ void k_init(const float* __restrict__ a_h,
                       const float* __restrict__ W_ent,
                       const float* __restrict__ W_rel,
                       const float* __restrict__ a_o,
                       const float* __restrict__ rel,
                       const float* __restrict__ x) {
    int tid = threadIdx.x;  // 256
    if (blockIdx.x < 256) {
        int i = blockIdx.x * 256 + tid;
        int stride = 256 * 256;
        if (i == 0) { g_nneed = 0; g_nmask = 0; }
        for (int idx = i; idx < 5 * NND; idx += stride) {
            int which = idx / NND, j = idx % NND;
            if (which == 0) g_cnt[j] = 0;
            else if (which == 1) g_cur[j] = 0;
            else if (which == 2) g_mask[j] = 0;
            else if (which == 3) g_needflag[j] = 0;
            else g_need_list[j] = 0;
        }
    } else {
        const int T1 = 400 * 128, T2 = 400 * 128, T3 = 240 * 128;
        const int T4 = 400 * 224, T5 = 240 * 224, T6 = 384 * 128;
        const int TP = T1 + T2 + T3 + T4 + T5 + T6;
        const int TX = (NND + 128) * 32;
        int idx = (blockIdx.x - 256) * 256 + tid;
        int stride = 512 * 256;
        for (int q = idx; q < TP + TX; q += stride) {
            if (q < TP) {
                int i = q;
                float v = 0.f;
                if (i < T1) {
                    int r = i >> 7, k = i & 127;
                    if (k < 100) v = (r < 200) ? a_h[(size_t)r * 300 + 100 + k]
                                               : W_ent[(size_t)k * 200 + (r - 200)];
                    g_Bent[i] = wmma::__float_to_tf32(v);
                } else if (i < T1 + T2) {
                    int j = i - T1; int r = j >> 7, k = j & 127;
                    if (k < 100) v = (r < 200) ? a_h[(size_t)r * 300 + 200 + k]
                                               : W_rel[(size_t)k * 200 + (r - 200)];
                    g_Brel[j] = wmma::__float_to_tf32(v);
                } else if (i < T1 + T2 + T3) {
                    int j = i - T1 - T2; int r = j >> 7, k = j & 127;
                    if (k < 100 && r < 200) v = a_h[(size_t)r * 300 + k];
                    g_Bsrc[j] = wmma::__float_to_tf32(v);
                } else if (i < T1 + T2 + T3 + T4) {
                    int j = i - T1 - T2 - T3; int r = j / 224, k = j % 224;
                    if (k < 200) v = (r < 200) ? a_o[(size_t)r * 600 + 200 + k]
                                               : a_o[(size_t)(r - 200) * 600 + k];
                    g_Bl2[j] = wmma::__float_to_tf32(v);
                } else if (i < T1 + T2 + T3 + T4 + T5) {
                    int j = i - T1 - T2 - T3 - T4; int r = j / 224, k = j % 224;
                    if (k < 200 && r < 200) v = a_o[(size_t)r * 600 + 400 + k];
                    g_Brp2[j] = wmma::__float_to_tf32(v);
                } else {
                    int j = i - T1 - T2 - T3 - T4 - T5; int r = j >> 7, k = j & 127;
                    if (k < 100 && r < 200) v = rel[(size_t)r * 100 + k];
                    g_relt[j] = wmma::__float_to_tf32(v);
                }
            } else {
                int i = q - TP;
                int row = i >> 5, c = i & 31;
                float4 v = make_float4(0.f, 0.f, 0.f, 0.f);
                if (row < NND && c < 25) {
                    v = *(const float4*)(x + (size_t)row * FINN + c * 4);
                    v.x = wmma::__float_to_tf32(v.x);
                    v.y = wmma::__float_to_tf32(v.y);
                    v.z = wmma::__float_to_tf32(v.z);
                    v.w = wmma::__float_to_tf32(v.w);
                }
                ((float4*)g_xt)[i] = v;
            }
        }
    }
}

// he table, t2map, combined logit vectors, mask set
__global__ void k_pre_small(const int* __restrict__ bi,
                            const float* __restrict__ wt2,
                            const float* __restrict__ bt2,
                            const int* __restrict__ etype,
                            const float* __restrict__ a_h,
                            const float* __restrict__ a2_h,
                            const float* __restrict__ a_o,
                            const float* __restrict__ a2_o) {
    int blk = blockIdx.x;
    int tid = threadIdx.x;  // 256
    if (blk < BATCH) {
        if (tid < HD) {
            float tf = (float)bi[blk * 4 + 3];
            float arg = __fadd_rn(__fmul_rn(tf, wt2[tid]), bt2[tid]);
            g_he[blk * HD + tid] = (float)cos((double)arg);
        }
    } else if (blk == BATCH) {
        if (tid < NREL) g_t2map[tid] = etype[tid];
    } else if (blk == BATCH + 1 || blk == BATCH + 2) {
        int h = blk - (BATCH + 1);
        if (tid < FINN) {
            float s0 = 0.f, s1 = 0.f, s2 = 0.f;
            for (int o = 0; o < NHID; o++) {
                float a2v = a2_h[h * NHID + o];
                const float* row = a_h + (size_t)h * NHID * 300 + (size_t)o * 300;
                s0 += row[tid] * a2v;
                s1 += row[100 + tid] * a2v;
                s2 += row[200 + tid] * a2v;
            }
            g_vs1[h * FINN + tid] = s0;
            g_vd1[h * FINN + tid] = s1;
            g_vr1[h * FINN + tid] = s2;
        }
    } else if (blk == BATCH + 3) {
        if (tid < D2) {
            float s0 = 0.f, s1 = 0.f, s2 = 0.f;
            for (int o = 0; o < D2; o++) {
                float a2v = a2_o[o];
                const float* row = a_o + (size_t)o * 600;
                s0 += row[tid] * a2v;
                s1 += row[200 + tid] * a2v;
                s2 += row[400 + tid] * a2v;
            }
            g_vs2[tid] = s0;
            g_vd2[tid] = s1;
            g_vr2[tid] = s2;
        }
    } else {
        for (int b = tid; b < BATCH; b += 256) {
            int node = bi[b * 4 + 2];
            g_mask[node] = 1;
            g_needflag[node] = 1;
        }
    }
}

// fused: hist_flags (blocks < HB) + xnvecs (blocks >= HB); 256 threads
#define HB 3125
__global__ void k_hx(const int* __restrict__ el, const float* __restrict__ x) {
    int tid = threadIdx.x;
    if (blockIdx.x < HB) {
        int e = blockIdx.x * 256 + tid;
        if (e >= EE) return;
        int e0 = el[e];
        int e1 = el[EE + e];
        atomicAdd(&g_cnt[e0], 1);
        if (g_mask[e0]) g_needflag[e1] = 1;
    } else {
        int warp = (blockIdx.x - HB) * 8 + (tid >> 5);
        int lane = tid & 31;
        if (warp >= NND) return;
        const float* row = x + (size_t)warp * FINN;
        float ss, a0 = 0.f, a1 = 0.f, b0 = 0.f, b1 = 0.f;
        float v0 = 0.f, v1 = 0.f, v2 = 0.f, v3 = 0.f;
        int k = lane;
        v0 = row[k];
        if (k + 32 < FINN) v1 = row[k + 32];
        if (k + 64 < FINN) v2 = row[k + 64];
        if (k + 96 < FINN) v3 = row[k + 96];
        ss = v0 * v0 + v1 * v1 + v2 * v2 + v3 * v3;
        a0 += v0 * g_vs1[k];        a1 += v0 * g_vs1[FINN + k];
        b0 += v0 * g_vd1[k];        b1 += v0 * g_vd1[FINN + k];
        if (k + 32 < FINN) {
            a0 += v1 * g_vs1[k+32]; a1 += v1 * g_vs1[FINN+k+32];
            b0 += v1 * g_vd1[k+32]; b1 += v1 * g_vd1[FINN+k+32];
        }
        if (k + 64 < FINN) {
            a0 += v2 * g_vs1[k+64]; a1 += v2 * g_vs1[FINN+k+64];
            b0 += v2 * g_vd1[k+64]; b1 += v2 * g_vd1[FINN+k+64];
        }
        if (k + 96 < FINN) {
            a0 += v3 * g_vs1[k+96]; a1 += v3 * g_vs1[FINN+k+96];
            b0 += v3 * g_vd1[k+96]; b1 += v3 * g_vd1[FINN+k+96];
        }
        for (int o = 16; o > 0; o >>= 1) {
            ss += __shfl_xor_sync(0xffffffffu, ss, o);
            a0 += __shfl_xor_sync(0xffffffffu, a0, o);
            a1 += __shfl_xor_sync(0xffffffffu, a1, o);
            b0 += __shfl_xor_sync(0xffffffffu, b0, o);
            b1 += __shfl_xor_sync(0xffffffffu, b1, o);
        }
        if (lane == 0) {
            g_invn[warp] = 1.f / fmaxf(sqrtf(ss), 1e-12f);
            g_ps1[warp] = a0;
            g_ps1[NND + warp] = a1;
            g_pd1[warp] = b0;
            g_pd1[NND + warp] = b1;
        }
    }
}

// block 0: smem-staged vectorized scan; blocks 1+: compaction
// dynamic smem (block 0 only uses it): 50176 ints = 200704 B
#define SCAN_SMEM (50176 * 4)
__global__ void __launch_bounds__(1024)
k_scan_compact() {
    extern __shared__ int scnt[];
    int t = threadIdx.x;  // 1024
    if (blockIdx.x == 0) {
        // stage all counts in smem (coalesced int4; NND % 4 == 0)
        for (int i = t; i < NND / 4; i += 1024)
            ((int4*)scnt)[i] = ((const int4*)g_cnt)[i];
        __syncthreads();
        const int CH = 49;  // 1024*49 = 50176 >= 50000
        int base = t * CH;
        int s = 0;
        for (int i = 0; i < CH; i++) {
            int idx = base + i;
            if (idx < NND) s += scnt[idx];
        }
        // block-wide exclusive scan via warp shuffles
        int lane = t & 31, wid = t >> 5;
        int ps = s;
#pragma unroll
        for (int o = 1; o < 32; o <<= 1) {
            int v = __shfl_up_sync(0xffffffffu, ps, o);
            if (lane >= o) ps += v;
        }
        __shared__ int wsum[32];
        if (lane == 31) wsum[wid] = ps;
        __syncthreads();
        if (wid == 0) {
            int w = wsum[lane];
#pragma unroll
            for (int o = 1; o < 32; o <<= 1) {
                int v = __shfl_up_sync(0xffffffffu, w, o);
                if (lane >= o) w += v;
            }
            wsum[lane] = w;
        }
        __syncthreads();
        int run = ps - s + (wid > 0 ? wsum[wid - 1] : 0);
        for (int i = 0; i < CH; i++) {
            int idx = base + i;
            if (idx < NND) {
                g_rowptr[idx] = run;
                run += scnt[idx];  // LDS chain, ~29 cyc/step
            }
        }
        if (t == 1023) g_rowptr[NND] = run;
    } else {
        int stride = (gridDim.x - 1) * 1024;
        for (int n = (blockIdx.x - 1) * 1024 + t; n < NND; n += stride) {
            if (g_needflag[n]) {
                int idx = atomicAdd(&g_nneed, 1);
                g_need_list[idx] = n;
                g_need_idx[n] = idx;
            }
            if (g_mask[n]) {
                int j = atomicAdd(&g_nmask, 1);
                g_mask_list[j] = n;
            }
        }
    }
}

// ---------------- persistent-A tf32 GEMM, K=128, BM=96 (2 blocks/SM) -------
// z=0: big = xt@Bent^T (5 panels); z=1: relC = relt@Brel^T (5 panels);
// z=2: xs1 = xt[need]@Bsrc^T (3 panels); z=3: his broadcast (streaming).
__global__ void __launch_bounds__(320)
k_gemm_pa(const int* __restrict__ nneedp, float* __restrict__ out) {
    const int BM = 96, BN = 80, K = 128, LDS = 132, LDC = 400;
    int tid = threadIdx.x;
    int z = blockIdx.z;
    if (z == 3) {
        const size_t TOT4 = (size_t)BATCH * BATCH * (HD / 4);
        const size_t OFF4 = ((size_t)NND * D2) / 4;
        const float4* he4 = (const float4*)g_he;
        float4* o4 = (float4*)out;
        size_t idx = (size_t)blockIdx.x * 320 + tid;
        size_t stride = (size_t)gridDim.x * 320;
        for (size_t j = idx; j < TOT4; j += stride) {
            int c = (int)(j % (HD / 4));
            int b1 = (int)(j / ((size_t)BATCH * (HD / 4)));
            o4[OFF4 + j] = he4[b1 * (HD / 4) + c];
        }
        return;
    }
    extern __shared__ __align__(16) float smem[];
    float* As = smem;
    float* Bs = smem + BM * LDS;
    const float* A; const float* B; float* C;
    int M, panels;
    const int* glist = nullptr;
    if (z == 0)      { A = g_xt;   B = g_Bent; C = g_big;  M = NND;     panels = 5; }
    else if (z == 1) { A = g_relt; B = g_Brel; C = g_relC; M = NREL;    panels = 5; }
    else             { A = g_xt;   B = g_Bsrc; C = g_xs1;  M = *nneedp; panels = 3;
                       glist = g_need_list; }
    int m0 = blockIdx.x * BM;
    if (m0 >= M) return;
    int wid = tid >> 5;
    int wm = wid & 1;
    int wn = wid >> 1;

    for (int i = tid; i < (BM * K) / 4; i += 320) {
        int m = i >> 5;
        int k4 = (i & 31) << 2;
        int row = glist ? glist[m0 + m] : (m0 + m);
        unsigned int daddr = (unsigned int)__cvta_generic_to_shared(&As[m * LDS + k4]);
        cp16(daddr, A + (size_t)row * K + k4);
    }
    for (int i = tid; i < (BN * K) / 4; i += 320) {
        int o = i >> 5;
        int k4 = (i & 31) << 2;
        unsigned int daddr = (unsigned int)__cvta_generic_to_shared(&Bs[o * LDS + k4]);
        cp16(daddr, B + (size_t)o * K + k4);
    }
    asm volatile("cp.async.commit_group;\n" ::: "memory");
    asm volatile("cp.async.wait_group 0;\n" ::: "memory");
    __syncthreads();

    for (int pnl = 0; pnl < panels; pnl++) {
        wmma::fragment<wmma::accumulator, 16, 16, 8, float> c[3];
#pragma unroll
        for (int i = 0; i < 3; i++) wmma::fill_fragment(c[i], 0.f);
#pragma unroll
        for (int ks = 0; ks < K; ks += 8) {
            wmma::fragment<wmma::matrix_b, 16, 16, 8, wmma::precision::tf32,
                           wmma::col_major> b;
            wmma::load_matrix_sync(b, &Bs[(wn * 16) * LDS + ks], LDS);
#pragma unroll
            for (int i = 0; i < 3; i++) {
                wmma::fragment<wmma::matrix_a, 16, 16, 8, wmma::precision::tf32,
                               wmma::row_major> a;
                wmma::load_matrix_sync(a, &As[(wm * 48 + i * 16) * LDS + ks], LDS);
                wmma::mma_sync(c[i], a, b, c[i]);
            }
        }
        __syncthreads();
        if (pnl + 1 < panels) {
            for (int i = tid; i < (BN * K) / 4; i += 320) {
                int o = i >> 5;
                int k4 = (i & 31) << 2;
                unsigned int daddr =
                    (unsigned int)__cvta_generic_to_shared(&Bs[o * LDS + k4]);
                cp16(daddr, B + (size_t)((pnl + 1) * BN + o) * K + k4);
            }
            asm volatile("cp.async.commit_group;\n" ::: "memory");
        }
#pragma unroll
        for (int i = 0; i < 3; i++) {
            int gm0 = m0 + wm * 48 + i * 16;
            wmma::store_matrix_sync(&C[(size_t)gm0 * LDC + pnl * BN + wn * 16],
                                    c[i], LDC, wmma::mem_row_major);
        }
        if (pnl + 1 < panels) {
            asm volatile("cp.async.wait_group 0;\n" ::: "memory");
        }
        __syncthreads();
    }
}

// fused: scatter (blocks < 3125) + misc1 (blocks 3125..3374); 256 threads
__global__ void k_scat_misc(const int* __restrict__ el,
                            const int* __restrict__ etype,
                            const float* __restrict__ rel) {
    int tid = threadIdx.x;
    if (blockIdx.x < 3125) {
        int e = blockIdx.x * 256 + tid;
        if (e >= EE) return;
        int e0 = el[e];
        int pos = g_rowptr[e0] + atomicAdd(&g_cur[e0], 1);
        g_csr_e1[pos] = el[EE + e];
        g_csr_t[pos] = etype[e];
        return;
    }
    int blk = blockIdx.x - 3125;
    if (blk < 50) {
        int w = blk * 8 + (tid >> 5);
        int lane = tid & 31;
        if (w >= 2 * NREL) return;
        int h = w / NREL, t = w % NREL;
        const float* rrow = rel + (size_t)t * 100;
        float s = 0.f;
        for (int kk = lane; kk < 100; kk += 32) s += rrow[kk] * g_vr1[h * FINN + kk];
        for (int o = 16; o > 0; o >>= 1) s += __shfl_xor_sync(0xffffffffu, s, o);
        if (lane == 0) g_pr1[h * NREL + t] = s;
    } else if (blk < 225) {
        int idx = (blk - 50) * 256 + tid;
        if (idx < NREL * 224) {
            int t = idx / 224, kk = idx % 224;
            float v = 0.f;
            if (kk < 200) v = g_relC[(size_t)g_t2map[t] * 400 + 200 + kk];
            g_RT2g[idx] = wmma::__float_to_tf32(v);
        }
    } else {
        int w = (blk - 225) * 8 + (tid >> 5);
        int lane = tid & 31;
        if (w >= NREL) return;
        const float* rrow = g_relC + (size_t)g_t2map[w] * 400 + 200;
        float s = 0.f;
        for (int kk = lane; kk < D2; kk += 32) s += rrow[kk] * g_vr2[kk];
        for (int o = 16; o > 0; o >>= 1) s += __shfl_xor_sync(0xffffffffu, s, o);
        if (lane == 0) g_pr2[w] = s;
    }
}

// layer-1 aggregation: staged weights + 4x-unrolled high-MLP edge loop
__global__ void k_agg1() {
    __shared__ float sw0[128], sw1[128];
    __shared__ int se1[128], st[128];
    __shared__ float redA[4], redB[4];
    int d = threadIdx.x;  // 128
    int wid = d >> 5, lane = d & 31;
    int nneed = g_nneed;
    for (int i = blockIdx.x; i < nneed; i += gridDim.x) {
        int n = g_need_list[i];
        float ps_a = g_ps1[n];
        float ps_b = g_ps1[NND + n];
        int s = g_rowptr[n], e = g_rowptr[n + 1];
        float acc0 = 0.f, acc1 = 0.f, ws0 = 0.f, ws1 = 0.f;
        for (int cs = s; cs < e; cs += 128) {
            int cnt = min(128, e - cs);
            __syncthreads();
            if (d < cnt) {
                int e1 = g_csr_e1[cs + d];
                int t = g_csr_t[cs + d];
                se1[d] = e1;
                st[d] = t;
                sw0[d] = expf(lrelu_neg(ps_a + g_pd1[e1] + g_pr1[t]));
                sw1[d] = expf(lrelu_neg(ps_b + g_pd1[NND + e1] + g_pr1[NREL + t]));
            }
            __syncthreads();
            int jj = 0;
            if (d < NHID) {
                float a0x = 0.f, a0y = 0.f, a1x = 0.f, a1y = 0.f;
                float w0x = 0.f, w0y = 0.f, w1x = 0.f, w1y = 0.f;
                for (; jj + 4 <= cnt; jj += 4) {
                    const float* B0 = g_big + (size_t)se1[jj] * 400;
                    const float* B1 = g_big + (size_t)se1[jj + 1] * 400;
                    const float* B2 = g_big + (size_t)se1[jj + 2] * 400;
                    const float* B3 = g_big + (size_t)se1[jj + 3] * 400;
                    const float* R0 = g_relC + (size_t)st[jj] * 400;
                    const float* R1 = g_relC + (size_t)st[jj + 1] * 400;
                    const float* R2 = g_relC + (size_t)st[jj + 2] * 400;
                    const float* R3 = g_relC + (size_t)st[jj + 3] * 400;
                    float b00 = B0[d], b01 = B1[d], b02 = B2[d], b03 = B3[d];
                    float b10 = B0[100 + d], b11 = B1[100 + d];
                    float b12 = B2[100 + d], b13 = B3[100 + d];
                    float r00 = R0[d], r01 = R1[d], r02 = R2[d], r03 = R3[d];
                    float r10 = R0[100 + d], r11 = R1[100 + d];
                    float r12 = R2[100 + d], r13 = R3[100 + d];
                    float w00 = sw0[jj], w01 = sw0[jj + 1];
                    float w02 = sw0[jj + 2], w03 = sw0[jj + 3];
                    float w10 = sw1[jj], w11 = sw1[jj + 1];
                    float w12 = sw1[jj + 2], w13 = sw1[jj + 3];
                    a0x += w00 * (b00 + r00);
                    a0y += w01 * (b01 + r01);
                    a0x += w02 * (b02 + r02);
                    a0y += w03 * (b03 + r03);
                    a1x += w10 * (b10 + r10);
                    a1y += w11 * (b11 + r11);
                    a1x += w12 * (b12 + r12);
                    a1y += w13 * (b13 + r13);
                    w0x += w00 + w02;
                    w0y += w01 + w03;
                    w1x += w10 + w12;
                    w1y += w11 + w13;
                }
                acc0 += a0x + a0y;
                acc1 += a1x + a1y;
                ws0 += w0x + w0y;
                ws1 += w1x + w1y;
                for (; jj < cnt; jj++) {
                    float w0 = sw0[jj], w1 = sw1[jj];
                    ws0 += w0;
                    ws1 += w1;
                    const float* bigrow = g_big + (size_t)se1[jj] * 400;
                    const float* rprow = g_relC + (size_t)st[jj] * 400;
                    acc0 += w0 * (bigrow[d] + rprow[d]);
                    acc1 += w1 * (bigrow[100 + d] + rprow[100 + d]);
                }
            }
        }
        float h0e = 0.f, h1e = 0.f;
        if (d < NHID) {
            float h0 = (g_xs1[(size_t)i * 400 + d] * ws0 + acc0) / (ws0 + 1e-12f);
            float h1 = (g_xs1[(size_t)i * 400 + 100 + d] * ws1 + acc1) / (ws1 + 1e-12f);
            h0e = (h0 > 0.f) ? h0 : expm1f(h0);
            h1e = (h1 > 0.f) ? h1 : expm1f(h1);
            g_x1[(size_t)i * 224 + d] = wmma::__float_to_tf32(h0e);
            g_x1[(size_t)i * 224 + 100 + d] = wmma::__float_to_tf32(h1e);
        } else if (d >= 100 && d < 124) {
            g_x1[(size_t)i * 224 + 100 + d] = 0.f;
        }
        float pa = 0.f, pb = 0.f;
        if (d < NHID) {
            pa = h0e * g_vd2[d] + h1e * g_vd2[100 + d];
            pb = h0e * g_vs2[d] + h1e * g_vs2[100 + d];
        }
        for (int o = 16; o > 0; o >>= 1) {
            pa += __shfl_xor_sync(0xffffffffu, pa, o);
            pb += __shfl_xor_sync(0xffffffffu, pb, o);
        }
        if (lane == 0) { redA[wid] = pa; redB[wid] = pb; }
        __syncthreads();
        if (d == 0) {
            g_pd2[i] = redA[0] + redA[1] + redA[2] + redA[3];
            g_ps2[i] = redB[0] + redB[1] + redB[2] + redB[3];
        }
        __syncthreads();
    }
}

// pipelined tf32 GEMM (K=224): z=0 l2 = x1@Bl2^T; z=1 rp2 = RT2g@Brp2^T
__global__ void __launch_bounds__(320)
k_gemm2(const int* __restrict__ nneedp) {
    const int BM = 128, BN = 80, BK = 32, K = 224;
    const int LDS = BK + 4;
    __shared__ __align__(16) float As[2][BM * LDS];
    __shared__ __align__(16) float Bs[2][BN * LDS];
    const float* A; const float* B; float* C;
    int M;
    if (blockIdx.z == 0) {
        A = g_x1; B = g_Bl2; C = g_l2; M = *nneedp;
    } else {
        if (blockIdx.x >= 2 || blockIdx.y >= 3) return;
        A = g_RT2g; B = g_Brp2; C = g_rp2; M = NREL;
    }
    int m0 = blockIdx.x * BM, o0 = blockIdx.y * BN;
    if (m0 >= M) return;
    int tid = threadIdx.x;
    int wid = tid >> 5;
    int wm = wid & 1;
    int wn = wid >> 1;

    wmma::fragment<wmma::accumulator, 16, 16, 8, float> c[4];
#pragma unroll
    for (int i = 0; i < 4; i++) wmma::fill_fragment(c[i], 0.f);

    auto prefetch = [&](int buf, int k0) {
#pragma unroll
        for (int s = 0; s < 4; s++) {
            int i = tid + s * 320;
            if (i < (BM * BK) / 4) {
                int m = i >> 3, k4 = (i & 7) << 2;
                unsigned int daddr = (unsigned int)__cvta_generic_to_shared(
                    &As[buf][m * LDS + k4]);
                cp16(daddr, A + (size_t)(m0 + m) * K + k0 + k4);
            }
        }
#pragma unroll
        for (int s = 0; s < 2; s++) {
            int i = tid + s * 320;
            if (i < (BN * BK) / 4) {
                int o = i >> 3, k4 = (i & 7) << 2;
                unsigned int daddr = (unsigned int)__cvta_generic_to_shared(
                    &Bs[buf][o * LDS + k4]);
                cp16(daddr, B + (size_t)(o0 + o) * K + k0 + k4);
            }
        }
        asm volatile("cp.async.commit_group;\n" ::: "memory");
    };

    int niter = K / BK;
    prefetch(0, 0);
    for (int it = 0; it < niter; it++) {
        int buf = it & 1;
        if (it + 1 < niter) {
            prefetch(buf ^ 1, (it + 1) * BK);
            asm volatile("cp.async.wait_group 1;\n" ::: "memory");
        } else {
            asm volatile("cp.async.wait_group 0;\n" ::: "memory");
        }
        __syncthreads();
#pragma unroll
        for (int ks = 0; ks < BK; ks += 8) {
            wmma::fragment<wmma::matrix_b, 16, 16, 8, wmma::precision::tf32,
                           wmma::col_major> b;
            wmma::load_matrix_sync(b, &Bs[buf][(wn * 16) * LDS + ks], LDS);
#pragma unroll
            for (int i = 0; i < 4; i++) {
                wmma::fragment<wmma::matrix_a, 16, 16, 8, wmma::precision::tf32,
                               wmma::row_major> a;
                wmma::load_matrix_sync(a, &As[buf][(wm * 64 + i * 16) * LDS + ks], LDS);
                wmma::mma_sync(c[i], a, b, c[i]);
            }
        }
        __syncthreads();
    }
#pragma unroll
    for (int i = 0; i < 4; i++) {
        int gm0 = m0 + wm * 64 + i * 16;
        wmma::store_matrix_sync(&C[(size_t)gm0 * 400 + o0 + wn * 16], c[i],
                                400, wmma::mem_row_major);
    }
}

// layer-2 aggregation: staged weights + 4x-unrolled edge loop
__global__ void k_agg2() {
    __shared__ float sw[256];
    __shared__ int si1[256], st[256];
    int d = threadIdx.x;  // 256
    int nmask = g_nmask;
    for (int m = blockIdx.x; m < nmask; m += gridDim.x) {
        int n = g_mask_list[m];
        int ii = g_need_idx[n];
        float ps = g_ps2[ii];
        int s = g_rowptr[n], e = g_rowptr[n + 1];
        float acc = 0.f, ws = 0.f;
        for (int cs = s; cs < e; cs += 256) {
            int cnt = min(256, e - cs);
            __syncthreads();
            if (d < cnt) {
                int e1 = g_csr_e1[cs + d];
                int t = g_csr_t[cs + d];
                int i1 = g_need_idx[e1];
                si1[d] = i1;
                st[d] = t;
                sw[d] = expf(lrelu_neg(ps + g_pd2[i1] + g_pr2[t]));
            }
            __syncthreads();
            if (d < D2) {
                int jj = 0;
                float ax = 0.f, ay = 0.f, wx = 0.f, wy = 0.f;
                for (; jj + 4 <= cnt; jj += 4) {
                    const float* L0 = g_l2 + (size_t)si1[jj] * 400;
                    const float* L1 = g_l2 + (size_t)si1[jj + 1] * 400;
                    const float* L2 = g_l2 + (size_t)si1[jj + 2] * 400;
                    const float* L3 = g_l2 + (size_t)si1[jj + 3] * 400;
                    const float* R0 = g_rp2 + (size_t)st[jj] * 400;
                    const float* R1 = g_rp2 + (size_t)st[jj + 1] * 400;
                    const float* R2 = g_rp2 + (size_t)st[jj + 2] * 400;
                    const float* R3 = g_rp2 + (size_t)st[jj + 3] * 400;
                    float l0 = L0[d], l1 = L1[d], l2 = L2[d], l3 = L3[d];
                    float r0 = R0[d], r1 = R1[d], r2 = R2[d], r3 = R3[d];
                    float w0 = sw[jj], w1 = sw[jj + 1], w2 = sw[jj + 2], w3 = sw[jj + 3];
                    ax += w0 * (l0 + r0);
                    ay += w1 * (l1 + r1);
                    ax += w2 * (l2 + r2);
                    ay += w3 * (l3 + r3);
                    wx += w0 + w2;
                    wy += w1 + w3;
                }
                acc += ax + ay;
                ws += wx + wy;
                for (; jj < cnt; jj++) {
                    float w = sw[jj];
                    ws += w;
                    acc += w * (g_l2[(size_t)si1[jj] * 400 + d] +
                                g_rp2[(size_t)st[jj] * 400 + d]);
                }
            }
        }
        if (d < D2) {
            float h = (g_l2[(size_t)ii * 400 + 200 + d] * ws + acc) / (ws + 1e-12f);
            g_x2[(size_t)ii * D2 + d] = (h > 0.f) ? h : expm1f(h);
        }
        __syncthreads();
    }
}

// warp-per-node: out[n] = l2norm(invn[n]*euraw[n] + mask*x2[n])
__global__ void k_out(float* __restrict__ out) {
    int w = (blockIdx.x * blockDim.x + threadIdx.x) >> 5;
    int lane = threadIdx.x & 31;
    if (w >= NND) return;
    int n = w;
    int msk = g_mask[n];
    int ii = msk ? g_need_idx[n] : 0;
    float inv = g_invn[n];
    const float* eur = g_big + (size_t)n * 400 + 200;
    const float* x2r = g_x2 + (size_t)ii * D2;
    float vals[7];
    float ss = 0.f;
#pragma unroll
    for (int r = 0; r < 7; r++) {
        int kk = lane + r * 32;
        float v = 0.f;
        if (kk < D2) {
            v = inv * eur[kk];
            if (msk) v += x2r[kk];
        }
        vals[r] = v;
        ss += v * v;
    }
    for (int o = 16; o > 0; o >>= 1) ss += __shfl_xor_sync(0xffffffffu, ss, o);
    float scale = 1.f / fmaxf(sqrtf(ss), 1e-12f);
    float* dst = out + (size_t)n * D2;
#pragma unroll
    for (int r = 0; r < 7; r++) {
        int kk = lane + r * 32;
        if (kk < D2) dst[kk] = vals[r] * scale;
    }
}

// ---------------- launcher ----------------
extern "C" void kernel_launch(void* const* d_in, const int* in_sizes, int n_in,
                              void* d_out, int out_size) {
    const float* x     = (const float*)d_in[0];
    const float* rel   = (const float*)d_in[1];
    const float* wt2   = (const float*)d_in[2];
    const float* bt2   = (const float*)d_in[3];
    const float* W_ent = (const float*)d_in[4];
    const float* a_h   = (const float*)d_in[5];
    const float* a2_h  = (const float*)d_in[6];
    const float* W_rel = (const float*)d_in[7];
    const float* a_o   = (const float*)d_in[8];
    const float* a2_o  = (const float*)d_in[9];
    const int* el      = (const int*)d_in[10];
    const int* et      = (const int*)d_in[11];
    const int* bi      = (const int*)d_in[12];
    float* out = (float*)d_out;
    (void)in_sizes; (void)n_in; (void)out_size;

    void* p;
    cudaGetSymbolAddress(&p, g_nneed); const int* d_nneed = (const int*)p;

    const int GM96 = (NND + 95) / 96;     // 521
    const int GM = (NND + 127) / 128;     // 391
    const int SMEM_PA = (96 * 132 + 80 * 132) * 4;  // 92928 B -> 2 blocks/SM
    cudaFuncSetAttribute(k_gemm_pa, cudaFuncAttributeMaxDynamicSharedMemorySize,
                         SMEM_PA);
    cudaFuncSetAttribute(k_scan_compact, cudaFuncAttributeMaxDynamicSharedMemorySize,
                         SCAN_SMEM);

    k_init<<<768, 256>>>(a_h, W_ent, W_rel, a_o, rel, x);
    k_pre_small<<<BATCH + 5, 256>>>(bi, wt2, bt2, et, a_h, a2_h, a_o, a2_o);
    k_hx<<<HB + (NND + 7) / 8, 256>>>(el, x);
    k_scan_compact<<<50, 1024, SCAN_SMEM>>>();   // launch #4 (profiled)

    k_gemm_pa<<<dim3(GM96, 1, 4), 320, SMEM_PA>>>(d_nneed, out);

    k_scat_misc<<<3125 + 250, 256>>>(el, et, rel);
    k_agg1<<<8192, 128>>>();
    k_gemm2<<<dim3(GM, 5, 2), 320>>>(d_nneed);
    k_agg2<<<512, 256>>>();
    k_out<<<(NND * 32 + 255) / 256, 256>>>(out);
}